// round 14
// baseline (speedup 1.0000x reference)
#include <cuda_runtime.h>
#include <cuda_bf16.h>
#include <math.h>
#include <stdint.h>

// Problem constants
#define N_TOK   2048
#define DIM     512
#define POOLSZ  65536
#define HIDDEN  256
#define HID2    128         // HIDDEN/2 (bf16 pair words)
#define HID4    64          // HIDDEN/4 (s8 quad words)
#define CHID    128
#define KSEL    256
#define CAND2   1024        // candidate buffer depth per token
#define FLOORZ  2.4f        // floor = FLOORZ*sigma
#define FMARG   0.08f       // int8 filter safety margin (~6.7 sigma_err)

// int8 GEMM tiling (mma.sync m16n8k32.s8 + ldmatrix)
#define BM 128
#define BN 128
#define IRS 272             // smem row stride bytes (256 data + 16 pad; 17i mod 32 distinct)
#define ASZ (BM * IRS)      // 34816 bytes per operand
#define GEMM_SMEM_BYTES (2 * ASZ + 4 * 128 * 4)

// Device scratch
__device__ float              g_h[N_TOK * HIDDEN];            // fp32 hidden (fallback)
__device__ unsigned           g_hb[N_TOK * HID2];             // bf16x2 hidden (rescore)
__device__ unsigned           g_h8[N_TOK * HID4];             // s8x4 hidden (filter gemm)
__device__ float              g_hsc[N_TOK];                   // h scale per token
__device__ unsigned           g_w2t[(size_t)POOLSZ * HID2];   // bf16x2 Ws2^T [n][k] (32 MB)
__device__ unsigned           g_w2q[(size_t)POOLSZ * HID4];   // s8x4  Ws2^T [n][k] (16 MB)
__device__ float              g_wsc[POOLSZ];                  // W col scale
__device__ float              g_wsci[POOLSZ];                 // 1/scale
__device__ float              g_floor[N_TOK];                 // margin-adjusted floor
__device__ unsigned           g_ccnt[N_TOK];
__device__ unsigned           g_cand[(size_t)N_TOK * CAND2];  // candidate indices
__device__ int                g_budget[N_TOK];
__device__ int                g_topidx[N_TOK * KSEL];
__device__ float              g_topw[N_TOK * KSEL];

// key helpers
__device__ __forceinline__ unsigned f2key(float s) {
    unsigned u = __float_as_uint(s);
    return (u & 0x80000000u) ? ~u : (u | 0x80000000u);
}
__device__ __forceinline__ float key2f(unsigned k) {
    return (k & 0x80000000u) ? __uint_as_float(k ^ 0x80000000u)
                             : __uint_as_float(~k);
}
__device__ __forceinline__ unsigned long long packc(unsigned key, unsigned idx) {
    return ((unsigned long long)key << 32) | (unsigned long long)(0xFFFFFFFFu - idx);
}
__device__ __forceinline__ unsigned packbf(float lo, float hi) {
    __nv_bfloat162 t;
    t.x = __float2bfloat16(lo);
    t.y = __float2bfloat16(hi);
    return *(unsigned*)&t;
}

__device__ __forceinline__ void cp_async16(uint32_t saddr, const void* gaddr) {
    asm volatile("cp.async.cg.shared.global [%0], [%1], 16;\n"
                 :: "r"(saddr), "l"(gaddr));
}
__device__ __forceinline__ void cp_commit() {
    asm volatile("cp.async.commit_group;\n");
}
template <int N> __device__ __forceinline__ void cp_wait() {
    asm volatile("cp.async.wait_group %0;\n" :: "n"(N));
}
__device__ __forceinline__ void ldsm_x4(uint32_t* r, uint32_t addr) {
    asm volatile("ldmatrix.sync.aligned.m8n8.x4.shared.b16 {%0,%1,%2,%3}, [%4];"
                 : "=r"(r[0]), "=r"(r[1]), "=r"(r[2]), "=r"(r[3]) : "r"(addr));
}
__device__ __forceinline__ void mma_s8(int* d, const uint32_t* a, const uint32_t* b) {
    asm volatile(
        "mma.sync.aligned.m16n8k32.row.col.s32.s8.s8.s32 "
        "{%0,%1,%2,%3}, {%4,%5,%6,%7}, {%8,%9}, {%0,%1,%2,%3};"
        : "+r"(d[0]), "+r"(d[1]), "+r"(d[2]), "+r"(d[3])
        : "r"(a[0]), "r"(a[1]), "r"(a[2]), "r"(a[3]), "r"(b[0]), "r"(b[1]));
}

// ---------------------------------------------------------------------------
// Kernel 1: per-column |W| max -> scales
// ---------------------------------------------------------------------------
__global__ void w2max_kernel(const float* __restrict__ Ws2) {
    int n = blockIdx.x * 256 + threadIdx.x;
    float mx = 0.f;
    for (int k = 0; k < HIDDEN; k++)
        mx = fmaxf(mx, fabsf(Ws2[(size_t)k * POOLSZ + n]));
    mx = fmaxf(mx, 1e-20f);
    g_wsc[n]  = mx * (1.0f / 127.0f);
    g_wsci[n] = 127.0f / mx;
}

// ---------------------------------------------------------------------------
// Kernel 2: convert Ws2 -> bf16x2 [n][k] rows + s8x4 [n][k] rows
// ---------------------------------------------------------------------------
__global__ void w2cvt_kernel(const float* __restrict__ Ws2) {
    __shared__ float ts[64][65];
    int tid = threadIdx.x;            // 0..255
    int n0 = blockIdx.x * 64;
    int k0 = blockIdx.y * 64;

#pragma unroll
    for (int i = 0; i < 16; i++) {
        int idx = tid + i * 256;
        int k = idx >> 6, n = idx & 63;
        ts[k][n] = Ws2[(size_t)(k0 + k) * POOLSZ + n0 + n];
    }
    __syncthreads();

    // bf16 pairs
#pragma unroll
    for (int i = 0; i < 8; i++) {
        int idx = tid + i * 256;
        int n = idx >> 5, w = idx & 31;
        g_w2t[(size_t)(n0 + n) * HID2 + (k0 >> 1) + w] =
            packbf(ts[2 * w][n], ts[2 * w + 1][n]);
    }
    // s8 quads
#pragma unroll
    for (int i = 0; i < 4; i++) {
        int idx = tid + i * 256;
        int n = idx >> 4, w = idx & 15;
        float inv = g_wsci[n0 + n];
        unsigned word = 0;
#pragma unroll
        for (int b = 0; b < 4; b++) {
            int q = (int)rintf(ts[4 * w + b][n] * inv);
            word |= (unsigned)(q & 0xFF) << (8 * b);
        }
        g_w2q[(size_t)(n0 + n) * HID4 + (k0 >> 2) + w] = word;
    }
}

// ---------------------------------------------------------------------------
// Kernel 3: hidden h = relu(x @ Ws1 + bs1) + per-token floor/scale/quantize
// ---------------------------------------------------------------------------
__global__ void hiddenq_kernel(const float* __restrict__ x,
                               const float* __restrict__ Ws1,
                               const float* __restrict__ bs1) {
    __shared__ float xs[16][DIM];     // 32 KB; reused as hs[16][256] after GEMM
    int tid = threadIdx.x;            // 0..255 (= hidden unit)
    int t0  = blockIdx.x * 16;

    const float4* xsrc = (const float4*)(x + (size_t)t0 * DIM);
    float4* xdst = (float4*)&xs[0][0];
    for (int i = tid; i < 16 * DIM / 4; i += 256) xdst[i] = xsrc[i];
    __syncthreads();

    float acc[16];
#pragma unroll
    for (int m = 0; m < 16; m++) acc[m] = 0.f;

    for (int i = 0; i < DIM; i += 4) {
        float w0 = Ws1[(i + 0) * HIDDEN + tid];
        float w1 = Ws1[(i + 1) * HIDDEN + tid];
        float w2 = Ws1[(i + 2) * HIDDEN + tid];
        float w3 = Ws1[(i + 3) * HIDDEN + tid];
#pragma unroll
        for (int m = 0; m < 16; m++) {
            float4 xv = *(const float4*)&xs[m][i];
            acc[m] += xv.x * w0 + xv.y * w1 + xv.z * w2 + xv.w * w3;
        }
    }
    __syncthreads();                  // xs reads done; reuse as hs

    float* hs = &xs[0][0];            // hs[m*256 + unit]
    float b = bs1[tid];
#pragma unroll
    for (int m = 0; m < 16; m++) {
        float hv = fmaxf(acc[m] + b, 0.f);
        g_h[(size_t)(t0 + m) * HIDDEN + tid] = hv;
        hs[m * 256 + tid] = hv;
        float other = __shfl_xor_sync(0xffffffffu, hv, 1);
        if ((tid & 1) == 0)
            g_hb[(size_t)(t0 + m) * HID2 + (tid >> 1)] = packbf(hv, other);
    }
    __syncthreads();

    // per-token floor + scale + s8 quantize (warp w handles tokens w, w+8)
    int warp = tid >> 5, lane = tid & 31;
    for (int t = warp; t < 16; t += 8) {
        const float* hr = hs + t * 256;
        float ss = 0.f, mx = 0.f;
#pragma unroll
        for (int j = 0; j < 8; j++) {
            float v = hr[lane + 32 * j];
            ss += v * v;
            mx = fmaxf(mx, v);
        }
#pragma unroll
        for (int off = 16; off > 0; off >>= 1) {
            ss += __shfl_xor_sync(0xffffffffu, ss, off);
            mx = fmaxf(mx, __shfl_xor_sync(0xffffffffu, mx, off));
        }
        float sh  = fmaxf(mx, 1e-20f) * (1.0f / 127.0f);
        float inv = 1.0f / sh;
        if (lane == 0) {
            g_floor[t0 + t] = FLOORZ * sqrtf(ss) * (1.0f / 16.0f) - FMARG;
            g_hsc[t0 + t]   = sh;
            g_ccnt[t0 + t]  = 0;
        }
        int base = lane * 8;
        unsigned w0 = 0, w1 = 0;
#pragma unroll
        for (int j = 0; j < 4; j++) {
            int q = (int)rintf(hr[base + j] * inv);
            w0 |= (unsigned)(q & 0xFF) << (8 * j);
        }
#pragma unroll
        for (int j = 0; j < 4; j++) {
            int q = (int)rintf(hr[base + 4 + j] * inv);
            w1 |= (unsigned)(q & 0xFF) << (8 * j);
        }
        g_h8[(size_t)(t0 + t) * HID4 + lane * 2]     = w0;
        g_h8[(size_t)(t0 + t) * HID4 + lane * 2 + 1] = w1;
    }
}

// ---------------------------------------------------------------------------
// Kernel 4: int8 filter GEMM. CTA 128x128, FULL K=256 in one smem stage,
// 8 warps (2m x 4n), warp tile 64x32, mma.sync.m16n8k32.s8 via ldmatrix.
// Epilogue: dequantized score >= floor-margin -> push candidate INDEX.
// ---------------------------------------------------------------------------
__global__ __launch_bounds__(256, 2) void gemm_kernel(const float* __restrict__ bs2) {
    extern __shared__ unsigned char smc[];
    float* bias_s  = (float*)(smc + 2 * ASZ);
    float* floor_s = bias_s + 128;
    float* sh_s    = floor_s + 128;
    float* sw_s    = sh_s + 128;

    int tid  = threadIdx.x;
    int warp = tid >> 5, lane = tid & 31;
    int wm = warp >> 2, wn = warp & 3;     // 2 x 4 warps
    int g  = lane >> 2, tg = lane & 3;
    int m0 = blockIdx.x * BM;
    int n0 = blockIdx.y * BN;

    for (int i = tid; i < 128; i += 256) {
        bias_s[i]  = bs2[n0 + i];
        floor_s[i] = g_floor[m0 + i];
        sh_s[i]    = g_hsc[m0 + i];
        sw_s[i]    = g_wsc[n0 + i];
    }

    uint32_t sbase = (uint32_t)__cvta_generic_to_shared(smc);

    // stage A (128 x 256B rows) and B (128 x 256B rows), 8 chunks/thread each
#pragma unroll
    for (int i = 0; i < 8; i++) {
        int s = tid + i * 256;
        int row = s >> 4, c = s & 15;
        cp_async16(sbase + (uint32_t)(row * IRS + c * 16),
                   g_h8 + (size_t)(m0 + row) * HID4 + c * 4);
    }
#pragma unroll
    for (int i = 0; i < 8; i++) {
        int s = tid + i * 256;
        int row = s >> 4, c = s & 15;
        cp_async16(sbase + (uint32_t)(ASZ + row * IRS + c * 16),
                   g_w2q + (size_t)(n0 + row) * HID4 + c * 4);
    }
    cp_commit();
    cp_wait<0>();
    __syncthreads();

    int lmat = lane >> 3, lrow = lane & 7;
    uint32_t a_off = (uint32_t)((wm * 64 + (lmat & 1) * 8 + lrow) * IRS +
                                (lmat >> 1) * 16);
    uint32_t b_off = (uint32_t)(ASZ + (wn * 32 + (lmat >> 1) * 8 + lrow) * IRS +
                                (lmat & 1) * 16);

    int acc[4][4][4];
#pragma unroll
    for (int mt = 0; mt < 4; mt++)
#pragma unroll
        for (int nt = 0; nt < 4; nt++)
#pragma unroll
            for (int c = 0; c < 4; c++) acc[mt][nt][c] = 0;

#pragma unroll
    for (int kk = 0; kk < 8; kk++) {           // 8 k32 steps
        uint32_t af[4][4];
#pragma unroll
        for (int mt = 0; mt < 4; mt++)
            ldsm_x4(af[mt], sbase + a_off + (uint32_t)(mt * 16 * IRS + kk * 32));
        uint32_t bf[2][4];
#pragma unroll
        for (int p = 0; p < 2; p++)
            ldsm_x4(bf[p], sbase + b_off + (uint32_t)(p * 16 * IRS + kk * 32));
#pragma unroll
        for (int mt = 0; mt < 4; mt++)
#pragma unroll
            for (int nt = 0; nt < 4; nt++)
                mma_s8(acc[mt][nt], af[mt], &bf[nt >> 1][(nt & 1) * 2]);
    }

    // epilogue: dequantize + filter, push indices only
#pragma unroll
    for (int mt = 0; mt < 4; mt++) {
#pragma unroll
        for (int c = 0; c < 4; c++) {
            int m_loc = wm * 64 + mt * 16 + g + ((c & 2) ? 8 : 0);
            float flo = floor_s[m_loc];
            float shm = sh_s[m_loc];
            int m = m0 + m_loc;
#pragma unroll
            for (int nt = 0; nt < 4; nt++) {
                int n_loc = wn * 32 + nt * 8 + 2 * tg + (c & 1);
                float s = __int2float_rn(acc[mt][nt][c]) * (shm * sw_s[n_loc])
                          + bias_s[n_loc];
                if (s >= flo) {
                    unsigned pos = atomicAdd(&g_ccnt[m], 1u);
                    if (pos < CAND2)
                        g_cand[(size_t)m * CAND2 + pos] = (unsigned)(n0 + n_loc);
                }
            }
        }
    }
}

// ---------------------------------------------------------------------------
// Kernel 5: complexity net -> budget[token]
// ---------------------------------------------------------------------------
__global__ void budget_kernel(const float* __restrict__ x,
                              const float* __restrict__ Wc1,
                              const float* __restrict__ bc1,
                              const float* __restrict__ Wc2,
                              const float* __restrict__ bc2) {
    __shared__ float xs[16][DIM];
    __shared__ float red[16][CHID];
    int tid = threadIdx.x;            // 0..127
    int t0  = blockIdx.x * 16;

    const float4* xsrc = (const float4*)(x + (size_t)t0 * DIM);
    float4* xdst = (float4*)&xs[0][0];
    for (int i = tid; i < 16 * DIM / 4; i += 128) xdst[i] = xsrc[i];
    __syncthreads();

    float acc[16];
#pragma unroll
    for (int m = 0; m < 16; m++) acc[m] = 0.f;

    for (int i = 0; i < DIM; i += 4) {
        float w0 = Wc1[(i + 0) * CHID + tid];
        float w1 = Wc1[(i + 1) * CHID + tid];
        float w2 = Wc1[(i + 2) * CHID + tid];
        float w3 = Wc1[(i + 3) * CHID + tid];
#pragma unroll
        for (int m = 0; m < 16; m++) {
            float4 xv = *(const float4*)&xs[m][i];
            acc[m] += xv.x * w0 + xv.y * w1 + xv.z * w2 + xv.w * w3;
        }
    }

    float b1  = bc1[tid];
    float wc2 = Wc2[tid];
#pragma unroll
    for (int m = 0; m < 16; m++) red[m][tid] = fmaxf(acc[m] + b1, 0.f) * wc2;
    __syncthreads();

    if (tid < 16) {
        float s = bc2[0];
        for (int t = 0; t < CHID; t++) s += red[tid][t];
        float sig   = 1.f / (1.f + expf(-s));
        float scale = sig * sig;
        float raw   = 100.f + 156.f * scale;
        raw = fminf(fmaxf(raw, 100.f), 256.f);
        g_budget[t0 + tid] = (int)rintf(raw);
    }
}

// ---------------------------------------------------------------------------
// Kernel 6: fallback — exact fp32 rescan for tokens with anomalous counts.
// Early-exits in the normal case.
// ---------------------------------------------------------------------------
#define HB 8192
__global__ void fallback_kernel(const float* __restrict__ Ws2,
                                const float* __restrict__ bs2) {
    int tok = blockIdx.x;
    unsigned cnt0 = g_ccnt[tok];
    if (cnt0 >= KSEL && cnt0 <= CAND2) return;

    __shared__ float    hs[HIDDEN];
    __shared__ unsigned hist[HB];
    __shared__ unsigned bsum[256];
    __shared__ unsigned s_thresh, s_cnt;
    int tid = threadIdx.x;            // 0..255

    for (int i = tid; i < HIDDEN; i += 256) hs[i] = g_h[(size_t)tok * HIDDEN + i];
    for (int i = tid; i < HB; i += 256) hist[i] = 0;
    if (tid == 0) s_cnt = 0;
    __syncthreads();

    for (int j0 = 0; j0 < POOLSZ; j0 += 256) {
        int j = j0 + tid;
        float s = bs2[j];
        for (int k = 0; k < HIDDEN; k += 4) {
            float4 hv = *(const float4*)&hs[k];
            s += hv.x * Ws2[(size_t)(k + 0) * POOLSZ + j];
            s += hv.y * Ws2[(size_t)(k + 1) * POOLSZ + j];
            s += hv.z * Ws2[(size_t)(k + 2) * POOLSZ + j];
            s += hv.w * Ws2[(size_t)(k + 3) * POOLSZ + j];
        }
        atomicAdd(&hist[f2key(s) >> 19], 1u);
    }
    __syncthreads();

    unsigned local = 0;
    int bb = tid * 32;
#pragma unroll
    for (int b = 0; b < 32; b++) local += hist[bb + b];
    bsum[tid] = local;
    __syncthreads();
    if (tid == 0) {
        unsigned cum = 0;
        int blk = 255;
        for (; blk > 0; blk--) {
            if (cum + bsum[blk] >= KSEL) break;
            cum += bsum[blk];
        }
        int b = blk * 32 + 31;
        for (;; b--) {
            unsigned c = hist[b];
            if (cum + c >= KSEL || b == 0) break;
            cum += c;
        }
        s_thresh = (unsigned)b << 19;
    }
    __syncthreads();
    unsigned th = s_thresh;

    for (int j0 = 0; j0 < POOLSZ; j0 += 256) {
        int j = j0 + tid;
        float s = bs2[j];
        for (int k = 0; k < HIDDEN; k += 4) {
            float4 hv = *(const float4*)&hs[k];
            s += hv.x * Ws2[(size_t)(k + 0) * POOLSZ + j];
            s += hv.y * Ws2[(size_t)(k + 1) * POOLSZ + j];
            s += hv.z * Ws2[(size_t)(k + 2) * POOLSZ + j];
            s += hv.w * Ws2[(size_t)(k + 3) * POOLSZ + j];
        }
        if (f2key(s) >= th) {
            unsigned pos = atomicAdd(&s_cnt, 1u);
            if (pos < CAND2)
                g_cand[(size_t)tok * CAND2 + pos] = (unsigned)j;
        }
    }
    __syncthreads();
    if (tid == 0) {
        unsigned c = s_cnt;
        g_ccnt[tok] = (c > CAND2) ? CAND2 : c;
    }
}

// ---------------------------------------------------------------------------
// Kernel 7: select — bf16 rescore candidates, bitonic sort, softmax, mask.
// ---------------------------------------------------------------------------
#define TPS 512
__global__ void select_kernel(const float* __restrict__ bs2) {
    __shared__ unsigned hw[HID2];             // 512 B
    __shared__ unsigned long long c[CAND2];   // 8 KB
    __shared__ float red[256];
    int tid = threadIdx.x;
    int tok = blockIdx.x;

    for (int i = tid; i < HID2; i += TPS) hw[i] = g_hb[(size_t)tok * HID2 + i];
    unsigned cnt = g_ccnt[tok];
    if (cnt > CAND2) cnt = CAND2;
    __syncthreads();

    for (int i = tid; i < CAND2; i += TPS) {
        if (i < (int)cnt) {
            unsigned n = g_cand[(size_t)tok * CAND2 + i];
            const unsigned* wrow = g_w2t + (size_t)n * HID2;
            float acc = bs2[n];
#pragma unroll 4
            for (int w = 0; w < HID2; w++) {
                float2 hf = __bfloat1622float2(*(const __nv_bfloat162*)&hw[w]);
                float2 wf = __bfloat1622float2(*(const __nv_bfloat162*)&wrow[w]);
                acc = fmaf(hf.x, wf.x, acc);
                acc = fmaf(hf.y, wf.y, acc);
            }
            c[i] = packc(f2key(acc), n);
        } else {
            c[i] = 0ULL;
        }
    }
    __syncthreads();

    for (unsigned k = 2; k <= CAND2; k <<= 1) {
        for (unsigned j = k >> 1; j > 0; j >>= 1) {
            for (unsigned i = tid; i < CAND2; i += TPS) {
                unsigned ixj = i ^ j;
                if (ixj > i) {
                    bool up = ((i & k) == 0);
                    unsigned long long a = c[i], b = c[ixj];
                    if (up ? (a > b) : (a < b)) { c[i] = b; c[ixj] = a; }
                }
            }
            __syncthreads();
        }
    }

    int bud = g_budget[tok];
    float smax = key2f((unsigned)(c[CAND2 - 1] >> 32));
    float ex = 0.f;
    unsigned long long v = 0ULL;
    if (tid < 256) {
        v  = c[CAND2 - 1 - tid];
        ex = expf(key2f((unsigned)(v >> 32)) - smax);
        red[tid] = ex;
    }
    __syncthreads();
    for (int s = 128; s > 0; s >>= 1) {
        if (tid < s) red[tid] += red[tid + s];
        __syncthreads();
    }
    if (tid < 256) {
        float w = ex / red[0];
        if (tid >= bud) w = 0.f;
        g_topidx[(size_t)tok * KSEL + tid] = (int)(0xFFFFFFFFu - (unsigned)(v & 0xFFFFFFFFull));
        g_topw[(size_t)tok * KSEL + tid]   = w;
    }
}

// ---------------------------------------------------------------------------
// Kernel 8: executor
// ---------------------------------------------------------------------------
__global__ void executor_kernel(const float* __restrict__ x,
                                const float* __restrict__ pool,
                                float* __restrict__ out) {
    __shared__ float xs[DIM];
    __shared__ float partial[8][DIM];
    int tok  = blockIdx.x;
    int tid  = threadIdx.x;
    int warp = tid >> 5;
    int lane = tid & 31;

    for (int i = tid; i < DIM; i += 256) xs[i] = x[(size_t)tok * DIM + i];
    __syncthreads();

    float acc[16];
#pragma unroll
    for (int j = 0; j < 16; j++) acc[j] = 0.f;

    for (int k = warp; k < KSEL; k += 8) {
        float w = g_topw[(size_t)tok * KSEL + k];
        if (w != 0.f) {
            int idx = g_topidx[(size_t)tok * KSEL + k];
            const float* row = pool + (size_t)idx * DIM;
            float r[16];
            float p = 0.f;
#pragma unroll
            for (int j = 0; j < 16; j++) {
                r[j] = __ldg(row + lane + 32 * j);
                p += xs[lane + 32 * j] * r[j];
            }
#pragma unroll
            for (int off = 16; off > 0; off >>= 1)
                p += __shfl_xor_sync(0xffffffffu, p, off);
            float act = tanhf(p) * w;
#pragma unroll
            for (int j = 0; j < 16; j++) acc[j] += act * r[j];
        }
    }

#pragma unroll
    for (int j = 0; j < 16; j++) partial[warp][lane + 32 * j] = acc[j];
    __syncthreads();

    for (int e = tid; e < DIM; e += 256) {
        float s = xs[e];
#pragma unroll
        for (int wp = 0; wp < 8; wp++) s += partial[wp][e];
        out[(size_t)tok * DIM + e] = s;
    }
}

// ---------------------------------------------------------------------------
extern "C" void kernel_launch(void* const* d_in, const int* in_sizes, int n_in,
                              void* d_out, int out_size) {
    const float* x    = (const float*)d_in[0];
    const float* pool = (const float*)d_in[1];
    const float* Wc1  = (const float*)d_in[2];
    const float* bc1  = (const float*)d_in[3];
    const float* Wc2  = (const float*)d_in[4];
    const float* bc2  = (const float*)d_in[5];
    const float* Ws1  = (const float*)d_in[6];
    const float* bs1  = (const float*)d_in[7];
    const float* Ws2  = (const float*)d_in[8];
    const float* bs2  = (const float*)d_in[9];
    float* out = (float*)d_out;

    cudaFuncSetAttribute(gemm_kernel,
                         cudaFuncAttributeMaxDynamicSharedMemorySize,
                         GEMM_SMEM_BYTES);

    w2max_kernel<<<POOLSZ / 256, 256>>>(Ws2);                      // 1
    dim3 tg(POOLSZ / 64, HIDDEN / 64);
    w2cvt_kernel<<<tg, 256>>>(Ws2);                                // 2
    hiddenq_kernel<<<N_TOK / 16, 256>>>(x, Ws1, bs1);              // 3

    dim3 ggrid(N_TOK / BM, POOLSZ / BN);   // x = m fast -> B slice reused in L2
    gemm_kernel<<<ggrid, 256, GEMM_SMEM_BYTES>>>(bs2);             // 4 (profiled slot)

    budget_kernel<<<N_TOK / 16, 128>>>(x, Wc1, bc1, Wc2, bc2);     // 5
    fallback_kernel<<<N_TOK, 256>>>(Ws2, bs2);                     // 6
    select_kernel<<<N_TOK, TPS>>>(bs2);                            // 7
    executor_kernel<<<N_TOK, 256>>>(x, pool, out);                 // 8
}

// round 15
// speedup vs baseline: 2.0989x; 2.0989x over previous
#include <cuda_runtime.h>
#include <cuda_fp16.h>
#include <math.h>
#include <stdint.h>

// Problem constants
#define N_TOK   2048
#define DIM     512
#define POOLSZ  65536
#define HIDDEN  256
#define HID2    128         // HIDDEN/2 (f16 pair words)
#define CHID    128
#define KSEL    256
#define CAND2   1024        // candidate buffer depth per token
#define FLOORZ  2.4f        // floor = FLOORZ*sigma  (E[count]=537, sd=23)
#define FMARG   0.02f       // fp16-accum filter safety margin

// GEMM tiling (f16 mma.sync m16n8k16, f16 accum + chunked f32 drain)
#define BM 128
#define BN 128
#define BKW 32              // k-pair words per stage (= 64 f16 k)
#define RS 36               // smem row stride in words (32 data + 4 pad)
#define SAW (BM * RS)       // 4608 words per A stage
#define SBW (BN * RS)       // 4608 words per B stage
#define GEMM_SMEM_WORDS (2 * SAW + 2 * SBW + BN + BM)
#define GEMM_SMEM_BYTES (GEMM_SMEM_WORDS * 4)

// Device scratch
__device__ float              g_h[N_TOK * HIDDEN];            // fp32 hidden (floor, fallback)
__device__ unsigned           g_hh[N_TOK * HID2];             // f16x2 hidden, k-major rows
__device__ unsigned           g_w2h[(size_t)POOLSZ * HID2];   // f16x2 Ws2^T rows [n][k] (32 MB)
__device__ float              g_floor[N_TOK];
__device__ unsigned           g_ccnt[N_TOK];
__device__ unsigned long long g_cand[(size_t)N_TOK * CAND2];
__device__ int                g_budget[N_TOK];
__device__ int                g_topidx[N_TOK * KSEL];
__device__ float              g_topw[N_TOK * KSEL];

// key helpers: monotonic float->uint mapping
__device__ __forceinline__ unsigned f2key(float s) {
    unsigned u = __float_as_uint(s);
    return (u & 0x80000000u) ? ~u : (u | 0x80000000u);
}
__device__ __forceinline__ float key2f(unsigned k) {
    return (k & 0x80000000u) ? __uint_as_float(k ^ 0x80000000u)
                             : __uint_as_float(~k);
}
__device__ __forceinline__ unsigned long long packc(unsigned key, unsigned idx) {
    return ((unsigned long long)key << 32) | (unsigned long long)(0xFFFFFFFFu - idx);
}
__device__ __forceinline__ unsigned packh(float lo, float hi) {
    __half2 t = __floats2half2_rn(lo, hi);
    return *(unsigned*)&t;
}

__device__ __forceinline__ void cp_async16(uint32_t saddr, const void* gaddr) {
    asm volatile("cp.async.cg.shared.global [%0], [%1], 16;\n"
                 :: "r"(saddr), "l"(gaddr));
}
__device__ __forceinline__ void cp_commit() {
    asm volatile("cp.async.commit_group;\n");
}
template <int N> __device__ __forceinline__ void cp_wait() {
    asm volatile("cp.async.wait_group %0;\n" :: "n"(N));
}
__device__ __forceinline__ void ldsm_x4(uint32_t* r, uint32_t addr) {
    asm volatile("ldmatrix.sync.aligned.m8n8.x4.shared.b16 {%0,%1,%2,%3}, [%4];"
                 : "=r"(r[0]), "=r"(r[1]), "=r"(r[2]), "=r"(r[3]) : "r"(addr));
}
// f16 x f16 -> f16 accumulate (legacy-pipe fast path), D/C = 2x f16x2 regs
__device__ __forceinline__ void mma_f16acc(uint32_t* d, const uint32_t* a,
                                           const uint32_t* b) {
    asm volatile(
        "mma.sync.aligned.m16n8k16.row.col.f16.f16.f16.f16 "
        "{%0,%1}, {%2,%3,%4,%5}, {%6,%7}, {%0,%1};"
        : "+r"(d[0]), "+r"(d[1])
        : "r"(a[0]), "r"(a[1]), "r"(a[2]), "r"(a[3]), "r"(b[0]), "r"(b[1]));
}

// ---------------------------------------------------------------------------
// Kernel 0: transpose-convert Ws2 fp32 [HIDDEN][POOLSZ] -> f16x2 rows [n][k]
// ---------------------------------------------------------------------------
__global__ void w2h_kernel(const float* __restrict__ Ws2) {
    __shared__ float ts[64][65];
    int tid = threadIdx.x;            // 0..255
    int n0 = blockIdx.x * 64;
    int k0 = blockIdx.y * 64;

#pragma unroll
    for (int i = 0; i < 16; i++) {
        int idx = tid + i * 256;
        int k = idx >> 6, n = idx & 63;
        ts[k][n] = Ws2[(size_t)(k0 + k) * POOLSZ + n0 + n];
    }
    __syncthreads();

#pragma unroll
    for (int i = 0; i < 8; i++) {
        int idx = tid + i * 256;
        int n = idx >> 5, w = idx & 31;
        g_w2h[(size_t)(n0 + n) * HID2 + (k0 >> 1) + w] =
            packh(ts[2 * w][n], ts[2 * w + 1][n]);
    }
}

// ---------------------------------------------------------------------------
// Kernel 1: scorer hidden h = relu(x @ Ws1 + bs1); stores fp32 + f16x2
// ---------------------------------------------------------------------------
__global__ void hidden_kernel(const float* __restrict__ x,
                              const float* __restrict__ Ws1,
                              const float* __restrict__ bs1) {
    __shared__ float xs[16][DIM];
    int tid = threadIdx.x;            // 0..255 (= hidden unit)
    int t0  = blockIdx.x * 16;

    const float4* xsrc = (const float4*)(x + (size_t)t0 * DIM);
    float4* xdst = (float4*)&xs[0][0];
    for (int i = tid; i < 16 * DIM / 4; i += 256) xdst[i] = xsrc[i];
    __syncthreads();

    float acc[16];
#pragma unroll
    for (int m = 0; m < 16; m++) acc[m] = 0.f;

    for (int i = 0; i < DIM; i += 4) {
        float w0 = Ws1[(i + 0) * HIDDEN + tid];
        float w1 = Ws1[(i + 1) * HIDDEN + tid];
        float w2 = Ws1[(i + 2) * HIDDEN + tid];
        float w3 = Ws1[(i + 3) * HIDDEN + tid];
#pragma unroll
        for (int m = 0; m < 16; m++) {
            float4 xv = *(const float4*)&xs[m][i];
            acc[m] += xv.x * w0 + xv.y * w1 + xv.z * w2 + xv.w * w3;
        }
    }

    float b = bs1[tid];
#pragma unroll
    for (int m = 0; m < 16; m++) {
        float hv = fmaxf(acc[m] + b, 0.f);
        g_h[(size_t)(t0 + m) * HIDDEN + tid] = hv;
        float other = __shfl_xor_sync(0xffffffffu, hv, 1);
        if ((tid & 1) == 0)
            g_hh[(size_t)(t0 + m) * HID2 + (tid >> 1)] = packh(hv, other);
    }
}

// ---------------------------------------------------------------------------
// Kernel 2: per-token floor = FLOORZ*||h||/16 - FMARG; zero candidate counter
// ---------------------------------------------------------------------------
__global__ void floor_kernel() {
    int tok  = blockIdx.x * 8 + (threadIdx.x >> 5);
    int lane = threadIdx.x & 31;
    const float* h = g_h + (size_t)tok * HIDDEN;
    float s = 0.f;
    for (int i = lane; i < HIDDEN; i += 32) { float v = h[i]; s += v * v; }
#pragma unroll
    for (int off = 16; off > 0; off >>= 1)
        s += __shfl_xor_sync(0xffffffffu, s, off);
    if (lane == 0) {
        g_floor[tok] = FLOORZ * sqrtf(s) * (1.0f / 16.0f) - FMARG;
        g_ccnt[tok]  = 0;
    }
}

// ---------------------------------------------------------------------------
// Kernel 3: f16 mma.sync GEMM (f16 accumulators, drained to f32 each K=64
// stage), ldmatrix fragment loads, fused candidate filter.
// CTA 128x128, 8 warps (2m x 4n), warp tile 64x32, cp.async double buffered.
// ---------------------------------------------------------------------------
__global__ __launch_bounds__(256, 2) void gemm_kernel(const float* __restrict__ bs2) {
    extern __shared__ unsigned smem[];             // word-addressed
    float* bias_s  = (float*)(smem + 2 * SAW + 2 * SBW);
    float* floor_s = bias_s + BN;

    int tid  = threadIdx.x;
    int warp = tid >> 5, lane = tid & 31;
    int wm = warp >> 2, wn = warp & 3;             // 2 x 4 warps
    int g  = lane >> 2, tg = lane & 3;
    int m0 = blockIdx.x * BM;
    int n0 = blockIdx.y * BN;

    for (int i = tid; i < BN; i += 256) bias_s[i]  = bs2[n0 + i];
    for (int i = tid; i < BM; i += 256) floor_s[i] = g_floor[m0 + i];

    uint32_t sbase = (uint32_t)__cvta_generic_to_shared(smem);
    const unsigned* gA = g_hh + (size_t)m0 * HID2;
    const unsigned* gB = g_w2h + (size_t)n0 * HID2;

    int srow = tid >> 3;                 // staging row group
    int sc16 = (tid & 7) << 2;           // word quad within 32-word k row

    int lmat = lane >> 3;                // ldmatrix constants
    int lrow = lane & 7;
    int a_row = wm * 64 + (lmat & 1) * 8 + lrow;
    int a_kw  = (lmat >> 1) * 4;
    int b_row = wn * 32 + (lmat >> 1) * 8 + lrow;
    int b_kw  = (lmat & 1) * 4;

    // prologue: stage 0
#pragma unroll
    for (int i = 0; i < 4; i++) {
        int row = srow + i * 32;
        cp_async16(sbase + (uint32_t)((row * RS + sc16) * 4),
                   gA + (size_t)row * HID2 + sc16);
    }
#pragma unroll
    for (int i = 0; i < 4; i++) {
        int row = srow + i * 32;
        cp_async16(sbase + (uint32_t)((2 * SAW + row * RS + sc16) * 4),
                   gB + (size_t)row * HID2 + sc16);
    }
    cp_commit();

    float acc[4][4][4];
#pragma unroll
    for (int mt = 0; mt < 4; mt++)
#pragma unroll
        for (int nt = 0; nt < 4; nt++)
#pragma unroll
            for (int c = 0; c < 4; c++) acc[mt][nt][c] = 0.f;

    for (int it = 0; it < HID2 / BKW; it++) {      // 4 stages (K=64 each)
        int buf = it & 1;
        if (it < HID2 / BKW - 1) {
            int kb   = (it + 1) * BKW;
            int nbuf = buf ^ 1;
#pragma unroll
            for (int i = 0; i < 4; i++) {
                int row = srow + i * 32;
                cp_async16(sbase + (uint32_t)((nbuf * SAW + row * RS + sc16) * 4),
                           gA + (size_t)row * HID2 + kb + sc16);
            }
#pragma unroll
            for (int i = 0; i < 4; i++) {
                int row = srow + i * 32;
                cp_async16(sbase + (uint32_t)((2 * SAW + nbuf * SBW + row * RS + sc16) * 4),
                           gB + (size_t)row * HID2 + kb + sc16);
            }
            cp_commit();
            cp_wait<1>();
        } else {
            cp_wait<0>();
        }
        __syncthreads();

        uint32_t abase = sbase + (uint32_t)(buf * SAW * 4);
        uint32_t bbase = sbase + (uint32_t)((2 * SAW + buf * SBW) * 4);

        // f16 accumulators for this stage (<=64 terms -> bounded error)
        uint32_t acch[4][4][2];
#pragma unroll
        for (int mt = 0; mt < 4; mt++)
#pragma unroll
            for (int nt = 0; nt < 4; nt++)
                acch[mt][nt][0] = acch[mt][nt][1] = 0u;

#pragma unroll
        for (int kk = 0; kk < 4; kk++) {           // 4 k16 steps per stage
            uint32_t af[4][4];
#pragma unroll
            for (int mt = 0; mt < 4; mt++)
                ldsm_x4(af[mt], abase +
                        (uint32_t)(((a_row + mt * 16) * RS + kk * 8 + a_kw) * 4));
            uint32_t bf[2][4];
#pragma unroll
            for (int p = 0; p < 2; p++)
                ldsm_x4(bf[p], bbase +
                        (uint32_t)(((b_row + p * 16) * RS + kk * 8 + b_kw) * 4));
#pragma unroll
            for (int mt = 0; mt < 4; mt++)
#pragma unroll
                for (int nt = 0; nt < 4; nt++)
                    mma_f16acc(acch[mt][nt], af[mt], &bf[nt >> 1][(nt & 1) * 2]);
        }

        // drain f16 stage sums into f32 accumulators
#pragma unroll
        for (int mt = 0; mt < 4; mt++)
#pragma unroll
            for (int nt = 0; nt < 4; nt++) {
                float2 lo = __half22float2(*(__half2*)&acch[mt][nt][0]);
                float2 hi = __half22float2(*(__half2*)&acch[mt][nt][1]);
                acc[mt][nt][0] += lo.x;
                acc[mt][nt][1] += lo.y;
                acc[mt][nt][2] += hi.x;
                acc[mt][nt][3] += hi.y;
            }
        __syncthreads();
    }

    // epilogue: bias + candidate filter (no score store)
#pragma unroll
    for (int mt = 0; mt < 4; mt++) {
#pragma unroll
        for (int c = 0; c < 4; c++) {
            int m_loc = wm * 64 + mt * 16 + g + ((c & 2) ? 8 : 0);
            float flo = floor_s[m_loc];
            int m = m0 + m_loc;
#pragma unroll
            for (int nt = 0; nt < 4; nt++) {
                int n_loc = wn * 32 + nt * 8 + 2 * tg + (c & 1);
                float s = acc[mt][nt][c] + bias_s[n_loc];
                if (s >= flo) {
                    unsigned pos = atomicAdd(&g_ccnt[m], 1u);
                    if (pos < CAND2)
                        g_cand[(size_t)m * CAND2 + pos] =
                            packc(f2key(s), (unsigned)(n0 + n_loc));
                }
            }
        }
    }
}

// ---------------------------------------------------------------------------
// Kernel 4: complexity net -> budget[token]
// ---------------------------------------------------------------------------
__global__ void budget_kernel(const float* __restrict__ x,
                              const float* __restrict__ Wc1,
                              const float* __restrict__ bc1,
                              const float* __restrict__ Wc2,
                              const float* __restrict__ bc2) {
    __shared__ float xs[16][DIM];
    __shared__ float red[16][CHID];
    int tid = threadIdx.x;            // 0..127
    int t0  = blockIdx.x * 16;

    const float4* xsrc = (const float4*)(x + (size_t)t0 * DIM);
    float4* xdst = (float4*)&xs[0][0];
    for (int i = tid; i < 16 * DIM / 4; i += 128) xdst[i] = xsrc[i];
    __syncthreads();

    float acc[16];
#pragma unroll
    for (int m = 0; m < 16; m++) acc[m] = 0.f;

    for (int i = 0; i < DIM; i += 4) {
        float w0 = Wc1[(i + 0) * CHID + tid];
        float w1 = Wc1[(i + 1) * CHID + tid];
        float w2 = Wc1[(i + 2) * CHID + tid];
        float w3 = Wc1[(i + 3) * CHID + tid];
#pragma unroll
        for (int m = 0; m < 16; m++) {
            float4 xv = *(const float4*)&xs[m][i];
            acc[m] += xv.x * w0 + xv.y * w1 + xv.z * w2 + xv.w * w3;
        }
    }

    float b1  = bc1[tid];
    float wc2 = Wc2[tid];
#pragma unroll
    for (int m = 0; m < 16; m++) red[m][tid] = fmaxf(acc[m] + b1, 0.f) * wc2;
    __syncthreads();

    if (tid < 16) {
        float s = bc2[0];
        for (int t = 0; t < CHID; t++) s += red[tid][t];
        float sig   = 1.f / (1.f + expf(-s));
        float scale = sig * sig;
        float raw   = 100.f + 156.f * scale;
        raw = fminf(fmaxf(raw, 100.f), 256.f);
        g_budget[t0 + tid] = (int)rintf(raw);
    }
}

// ---------------------------------------------------------------------------
// Kernel 5: fallback — exact fp32 rescan for tokens with anomalous counts.
// Early-exits in the normal case.
// ---------------------------------------------------------------------------
#define HB 8192
__global__ void fallback_kernel(const float* __restrict__ Ws2,
                                const float* __restrict__ bs2) {
    int tok = blockIdx.x;
    unsigned cnt0 = g_ccnt[tok];
    if (cnt0 >= KSEL && cnt0 <= CAND2) return;

    __shared__ float    hs[HIDDEN];
    __shared__ unsigned hist[HB];
    __shared__ unsigned bsum[256];
    __shared__ unsigned s_thresh, s_cnt;
    int tid = threadIdx.x;            // 0..255

    for (int i = tid; i < HIDDEN; i += 256) hs[i] = g_h[(size_t)tok * HIDDEN + i];
    for (int i = tid; i < HB; i += 256) hist[i] = 0;
    if (tid == 0) s_cnt = 0;
    __syncthreads();

    for (int j0 = 0; j0 < POOLSZ; j0 += 256) {
        int j = j0 + tid;
        float s = bs2[j];
        for (int k = 0; k < HIDDEN; k += 4) {
            float4 hv = *(const float4*)&hs[k];
            s += hv.x * Ws2[(size_t)(k + 0) * POOLSZ + j];
            s += hv.y * Ws2[(size_t)(k + 1) * POOLSZ + j];
            s += hv.z * Ws2[(size_t)(k + 2) * POOLSZ + j];
            s += hv.w * Ws2[(size_t)(k + 3) * POOLSZ + j];
        }
        atomicAdd(&hist[f2key(s) >> 19], 1u);
    }
    __syncthreads();

    unsigned local = 0;
    int bb = tid * 32;
#pragma unroll
    for (int b = 0; b < 32; b++) local += hist[bb + b];
    bsum[tid] = local;
    __syncthreads();
    if (tid == 0) {
        unsigned cum = 0;
        int blk = 255;
        for (; blk > 0; blk--) {
            if (cum + bsum[blk] >= KSEL) break;
            cum += bsum[blk];
        }
        int b = blk * 32 + 31;
        for (;; b--) {
            unsigned c = hist[b];
            if (cum + c >= KSEL || b == 0) break;
            cum += c;
        }
        s_thresh = (unsigned)b << 19;
    }
    __syncthreads();
    unsigned th = s_thresh;

    for (int j0 = 0; j0 < POOLSZ; j0 += 256) {
        int j = j0 + tid;
        float s = bs2[j];
        for (int k = 0; k < HIDDEN; k += 4) {
            float4 hv = *(const float4*)&hs[k];
            s += hv.x * Ws2[(size_t)(k + 0) * POOLSZ + j];
            s += hv.y * Ws2[(size_t)(k + 1) * POOLSZ + j];
            s += hv.z * Ws2[(size_t)(k + 2) * POOLSZ + j];
            s += hv.w * Ws2[(size_t)(k + 3) * POOLSZ + j];
        }
        unsigned key = f2key(s);
        if (key >= th) {
            unsigned pos = atomicAdd(&s_cnt, 1u);
            if (pos < CAND2)
                g_cand[(size_t)tok * CAND2 + pos] = packc(key, (unsigned)j);
        }
    }
    __syncthreads();
    if (tid == 0) {
        unsigned c = s_cnt;
        g_ccnt[tok] = (c > CAND2) ? CAND2 : c;
    }
}

// ---------------------------------------------------------------------------
// Kernel 6: per-token select: bitonic sort of <=1024 packed candidates,
// softmax over top-256, budget mask.
// ---------------------------------------------------------------------------
#define TPS 512
__global__ void select_kernel() {
    __shared__ unsigned long long c[CAND2];
    __shared__ float red[256];
    int tid = threadIdx.x;
    int tok = blockIdx.x;

    unsigned cnt = g_ccnt[tok];
    if (cnt > CAND2) cnt = CAND2;
    for (int i = tid; i < CAND2; i += TPS)
        c[i] = (i < (int)cnt) ? g_cand[(size_t)tok * CAND2 + i] : 0ULL;
    __syncthreads();

    for (unsigned k = 2; k <= CAND2; k <<= 1) {
        for (unsigned j = k >> 1; j > 0; j >>= 1) {
            for (unsigned i = tid; i < CAND2; i += TPS) {
                unsigned ixj = i ^ j;
                if (ixj > i) {
                    bool up = ((i & k) == 0);
                    unsigned long long a = c[i], b = c[ixj];
                    if (up ? (a > b) : (a < b)) { c[i] = b; c[ixj] = a; }
                }
            }
            __syncthreads();
        }
    }

    int bud = g_budget[tok];
    float smax = key2f((unsigned)(c[CAND2 - 1] >> 32));
    float ex = 0.f;
    unsigned long long v = 0ULL;
    if (tid < 256) {
        v  = c[CAND2 - 1 - tid];
        ex = expf(key2f((unsigned)(v >> 32)) - smax);
        red[tid] = ex;
    }
    __syncthreads();
    for (int s = 128; s > 0; s >>= 1) {
        if (tid < s) red[tid] += red[tid + s];
        __syncthreads();
    }
    if (tid < 256) {
        float w = ex / red[0];
        if (tid >= bud) w = 0.f;
        g_topidx[(size_t)tok * KSEL + tid] = (int)(0xFFFFFFFFu - (unsigned)(v & 0xFFFFFFFFull));
        g_topw[(size_t)tok * KSEL + tid]   = w;
    }
}

// ---------------------------------------------------------------------------
// Kernel 7: executor (float4 gather)
// ---------------------------------------------------------------------------
__global__ void executor_kernel(const float* __restrict__ x,
                                const float* __restrict__ pool,
                                float* __restrict__ out) {
    __shared__ float xs[DIM];
    __shared__ float partial[8][DIM];
    int tok  = blockIdx.x;
    int tid  = threadIdx.x;
    int warp = tid >> 5;
    int lane = tid & 31;

    for (int i = tid; i < DIM; i += 256) xs[i] = x[(size_t)tok * DIM + i];
    __syncthreads();

    float4 acc4[4];
#pragma unroll
    for (int j = 0; j < 4; j++) acc4[j] = make_float4(0.f, 0.f, 0.f, 0.f);

    const float4* xs4 = (const float4*)xs;
    for (int k = warp; k < KSEL; k += 8) {
        float w = g_topw[(size_t)tok * KSEL + k];
        if (w != 0.f) {
            int idx = g_topidx[(size_t)tok * KSEL + k];
            const float4* row = (const float4*)(pool + (size_t)idx * DIM);
            float4 r[4];
            float p = 0.f;
#pragma unroll
            for (int j = 0; j < 4; j++) {
                r[j] = __ldg(row + lane + 32 * j);
                float4 xv = xs4[lane + 32 * j];
                p += xv.x * r[j].x + xv.y * r[j].y + xv.z * r[j].z + xv.w * r[j].w;
            }
#pragma unroll
            for (int off = 16; off > 0; off >>= 1)
                p += __shfl_xor_sync(0xffffffffu, p, off);
            float act = tanhf(p) * w;
#pragma unroll
            for (int j = 0; j < 4; j++) {
                acc4[j].x += act * r[j].x;
                acc4[j].y += act * r[j].y;
                acc4[j].z += act * r[j].z;
                acc4[j].w += act * r[j].w;
            }
        }
    }

    float4* part4 = (float4*)&partial[warp][0];
#pragma unroll
    for (int j = 0; j < 4; j++) part4[lane + 32 * j] = acc4[j];
    __syncthreads();

    for (int e = tid; e < DIM; e += 256) {
        float s = xs[e];
#pragma unroll
        for (int wp = 0; wp < 8; wp++) s += partial[wp][e];
        out[(size_t)tok * DIM + e] = s;
    }
}

// ---------------------------------------------------------------------------
extern "C" void kernel_launch(void* const* d_in, const int* in_sizes, int n_in,
                              void* d_out, int out_size) {
    const float* x    = (const float*)d_in[0];
    const float* pool = (const float*)d_in[1];
    const float* Wc1  = (const float*)d_in[2];
    const float* bc1  = (const float*)d_in[3];
    const float* Wc2  = (const float*)d_in[4];
    const float* bc2  = (const float*)d_in[5];
    const float* Ws1  = (const float*)d_in[6];
    const float* bs1  = (const float*)d_in[7];
    const float* Ws2  = (const float*)d_in[8];
    const float* bs2  = (const float*)d_in[9];
    float* out = (float*)d_out;

    cudaFuncSetAttribute(gemm_kernel,
                         cudaFuncAttributeMaxDynamicSharedMemorySize,
                         GEMM_SMEM_BYTES);

    dim3 tg(POOLSZ / 64, HIDDEN / 64);
    w2h_kernel<<<tg, 256>>>(Ws2);                                  // 1
    hidden_kernel<<<N_TOK / 16, 256>>>(x, Ws1, bs1);               // 2
    floor_kernel<<<N_TOK / 8, 256>>>();                            // 3

    dim3 ggrid(N_TOK / BM, POOLSZ / BN);   // x = m fast -> B slice reused in L2
    gemm_kernel<<<ggrid, 256, GEMM_SMEM_BYTES>>>(bs2);             // 4 (profiled slot)

    budget_kernel<<<N_TOK / 16, 128>>>(x, Wc1, bc1, Wc2, bc2);     // 5
    fallback_kernel<<<N_TOK, 256>>>(Ws2, bs2);                     // 6
    select_kernel<<<N_TOK, TPS>>>();                               // 7
    executor_kernel<<<N_TOK, 256>>>(x, pool, out);                 // 8
}

// round 16
// speedup vs baseline: 2.4444x; 1.1646x over previous
#include <cuda_runtime.h>
#include <cuda_fp16.h>
#include <math.h>
#include <stdint.h>

// Problem constants
#define N_TOK   2048
#define DIM     512
#define POOLSZ  65536
#define HIDDEN  256
#define HID2    128         // HIDDEN/2 (f16 pair words)
#define CHID    128
#define KSEL    256
#define CAND2   1024        // candidate buffer depth per token
#define FLOORZ  2.4f        // floor = FLOORZ*sigma  (E[count]=537, sd=23)
#define FMARG   0.03f       // f16 full-K accum filter margin (~20 sigma_err)

// GEMM tiling (f16 mma.sync m16n8k16, f16 accum, single final drain)
#define BM 128
#define BN 128
#define BKW 16              // k-pair words per stage (= 32 f16 k), 8 stages
#define RS 20               // smem row stride words (16 data + 4 pad; 5i mod 32 distinct)
#define SAW (BM * RS)       // 2560 words per A stage
#define SBW (BN * RS)       // 2560 words per B stage
#define GEMM_SMEM_WORDS (2 * SAW + 2 * SBW + BN + BM)
#define GEMM_SMEM_BYTES (GEMM_SMEM_WORDS * 4)

// Device scratch
__device__ float              g_h[N_TOK * HIDDEN];            // fp32 hidden (floor, fallback)
__device__ unsigned           g_hh[N_TOK * HID2];             // f16x2 hidden, k-major rows
__device__ unsigned           g_w2h[(size_t)POOLSZ * HID2];   // f16x2 Ws2^T rows [n][k] (32 MB)
__device__ float              g_floor[N_TOK];
__device__ unsigned           g_ccnt[N_TOK];
__device__ unsigned long long g_cand[(size_t)N_TOK * CAND2];
__device__ int                g_budget[N_TOK];
__device__ int                g_topidx[N_TOK * KSEL];
__device__ float              g_topw[N_TOK * KSEL];

// key helpers: monotonic float->uint mapping
__device__ __forceinline__ unsigned f2key(float s) {
    unsigned u = __float_as_uint(s);
    return (u & 0x80000000u) ? ~u : (u | 0x80000000u);
}
__device__ __forceinline__ float key2f(unsigned k) {
    return (k & 0x80000000u) ? __uint_as_float(k ^ 0x80000000u)
                             : __uint_as_float(~k);
}
__device__ __forceinline__ unsigned long long packc(unsigned key, unsigned idx) {
    return ((unsigned long long)key << 32) | (unsigned long long)(0xFFFFFFFFu - idx);
}
__device__ __forceinline__ unsigned packh(float lo, float hi) {
    __half2 t = __floats2half2_rn(lo, hi);
    return *(unsigned*)&t;
}

__device__ __forceinline__ void cp_async16(uint32_t saddr, const void* gaddr) {
    asm volatile("cp.async.cg.shared.global [%0], [%1], 16;\n"
                 :: "r"(saddr), "l"(gaddr));
}
__device__ __forceinline__ void cp_commit() {
    asm volatile("cp.async.commit_group;\n");
}
template <int N> __device__ __forceinline__ void cp_wait() {
    asm volatile("cp.async.wait_group %0;\n" :: "n"(N));
}
__device__ __forceinline__ void ldsm_x4(uint32_t* r, uint32_t addr) {
    asm volatile("ldmatrix.sync.aligned.m8n8.x4.shared.b16 {%0,%1,%2,%3}, [%4];"
                 : "=r"(r[0]), "=r"(r[1]), "=r"(r[2]), "=r"(r[3]) : "r"(addr));
}
// f16 x f16 -> f16 accumulate (double-rate legacy-pipe path)
__device__ __forceinline__ void mma_f16acc(uint32_t* d, const uint32_t* a,
                                           const uint32_t* b) {
    asm volatile(
        "mma.sync.aligned.m16n8k16.row.col.f16.f16.f16.f16 "
        "{%0,%1}, {%2,%3,%4,%5}, {%6,%7}, {%0,%1};"
        : "+r"(d[0]), "+r"(d[1])
        : "r"(a[0]), "r"(a[1]), "r"(a[2]), "r"(a[3]), "r"(b[0]), "r"(b[1]));
}

// ---------------------------------------------------------------------------
// Kernel 0: transpose-convert Ws2 fp32 [HIDDEN][POOLSZ] -> f16x2 rows [n][k]
// ---------------------------------------------------------------------------
__global__ void w2h_kernel(const float* __restrict__ Ws2) {
    __shared__ float ts[64][65];
    int tid = threadIdx.x;            // 0..255
    int n0 = blockIdx.x * 64;
    int k0 = blockIdx.y * 64;

#pragma unroll
    for (int i = 0; i < 16; i++) {
        int idx = tid + i * 256;
        int k = idx >> 6, n = idx & 63;
        ts[k][n] = Ws2[(size_t)(k0 + k) * POOLSZ + n0 + n];
    }
    __syncthreads();

#pragma unroll
    for (int i = 0; i < 8; i++) {
        int idx = tid + i * 256;
        int n = idx >> 5, w = idx & 31;
        g_w2h[(size_t)(n0 + n) * HID2 + (k0 >> 1) + w] =
            packh(ts[2 * w][n], ts[2 * w + 1][n]);
    }
}

// ---------------------------------------------------------------------------
// Kernel 1: scorer hidden h = relu(x @ Ws1 + bs1); stores fp32 + f16x2
// ---------------------------------------------------------------------------
__global__ void hidden_kernel(const float* __restrict__ x,
                              const float* __restrict__ Ws1,
                              const float* __restrict__ bs1) {
    __shared__ float xs[16][DIM];
    int tid = threadIdx.x;            // 0..255 (= hidden unit)
    int t0  = blockIdx.x * 16;

    const float4* xsrc = (const float4*)(x + (size_t)t0 * DIM);
    float4* xdst = (float4*)&xs[0][0];
    for (int i = tid; i < 16 * DIM / 4; i += 256) xdst[i] = xsrc[i];
    __syncthreads();

    float acc[16];
#pragma unroll
    for (int m = 0; m < 16; m++) acc[m] = 0.f;

    for (int i = 0; i < DIM; i += 4) {
        float w0 = Ws1[(i + 0) * HIDDEN + tid];
        float w1 = Ws1[(i + 1) * HIDDEN + tid];
        float w2 = Ws1[(i + 2) * HIDDEN + tid];
        float w3 = Ws1[(i + 3) * HIDDEN + tid];
#pragma unroll
        for (int m = 0; m < 16; m++) {
            float4 xv = *(const float4*)&xs[m][i];
            acc[m] += xv.x * w0 + xv.y * w1 + xv.z * w2 + xv.w * w3;
        }
    }

    float b = bs1[tid];
#pragma unroll
    for (int m = 0; m < 16; m++) {
        float hv = fmaxf(acc[m] + b, 0.f);
        g_h[(size_t)(t0 + m) * HIDDEN + tid] = hv;
        float other = __shfl_xor_sync(0xffffffffu, hv, 1);
        if ((tid & 1) == 0)
            g_hh[(size_t)(t0 + m) * HID2 + (tid >> 1)] = packh(hv, other);
    }
}

// ---------------------------------------------------------------------------
// Kernel 2: per-token floor = FLOORZ*||h||/16 - FMARG; zero candidate counter
// ---------------------------------------------------------------------------
__global__ void floor_kernel() {
    int tok  = blockIdx.x * 8 + (threadIdx.x >> 5);
    int lane = threadIdx.x & 31;
    const float* h = g_h + (size_t)tok * HIDDEN;
    float s = 0.f;
    for (int i = lane; i < HIDDEN; i += 32) { float v = h[i]; s += v * v; }
#pragma unroll
    for (int off = 16; off > 0; off >>= 1)
        s += __shfl_xor_sync(0xffffffffu, s, off);
    if (lane == 0) {
        g_floor[tok] = FLOORZ * sqrtf(s) * (1.0f / 16.0f) - FMARG;
        g_ccnt[tok]  = 0;
    }
}

// ---------------------------------------------------------------------------
// Kernel 3: f16 mma.sync GEMM, f16 accumulators across full K (single final
// drain), ldmatrix loads, fused candidate filter. CTA 128x128, 8 warps
// (2m x 4n), warp tile 64x32, BK=32 x 8 double-buffered stages, 3 CTAs/SM.
// ---------------------------------------------------------------------------
__global__ __launch_bounds__(256, 3) void gemm_kernel(const float* __restrict__ bs2) {
    extern __shared__ unsigned smem[];             // word-addressed
    float* bias_s  = (float*)(smem + 2 * SAW + 2 * SBW);
    float* floor_s = bias_s + BN;

    int tid  = threadIdx.x;
    int warp = tid >> 5, lane = tid & 31;
    int wm = warp >> 2, wn = warp & 3;             // 2 x 4 warps
    int g  = lane >> 2, tg = lane & 3;
    int m0 = blockIdx.x * BM;
    int n0 = blockIdx.y * BN;

    for (int i = tid; i < BN; i += 256) bias_s[i]  = bs2[n0 + i];
    for (int i = tid; i < BM; i += 256) floor_s[i] = g_floor[m0 + i];

    uint32_t sbase = (uint32_t)__cvta_generic_to_shared(smem);
    const unsigned* gA = g_hh + (size_t)m0 * HID2;
    const unsigned* gB = g_w2h + (size_t)n0 * HID2;

    // staging: 512 16B chunks per operand per stage; 2 chunks/thread
    int srow = tid >> 2;                 // 0..63 -> rows srow, srow+64
    int sc16 = (tid & 3) << 2;           // word quad within 16-word k row

    int lmat = lane >> 3;                // ldmatrix constants
    int lrow = lane & 7;
    int a_row = wm * 64 + (lmat & 1) * 8 + lrow;
    int a_kw  = (lmat >> 1) * 4;
    int b_row = wn * 32 + (lmat >> 1) * 8 + lrow;
    int b_kw  = (lmat & 1) * 4;

    // prologue: stage 0
#pragma unroll
    for (int i = 0; i < 2; i++) {
        int row = srow + i * 64;
        cp_async16(sbase + (uint32_t)((row * RS + sc16) * 4),
                   gA + (size_t)row * HID2 + sc16);
        cp_async16(sbase + (uint32_t)((2 * SAW + row * RS + sc16) * 4),
                   gB + (size_t)row * HID2 + sc16);
    }
    cp_commit();

    // f16 accumulators, carried across all 8 stages (256 K terms)
    uint32_t acch[4][4][2];
#pragma unroll
    for (int mt = 0; mt < 4; mt++)
#pragma unroll
        for (int nt = 0; nt < 4; nt++)
            acch[mt][nt][0] = acch[mt][nt][1] = 0u;

    for (int it = 0; it < HID2 / BKW; it++) {      // 8 stages (K=32 each)
        int buf = it & 1;
        if (it < HID2 / BKW - 1) {
            int kb   = (it + 1) * BKW;
            int nbuf = buf ^ 1;
#pragma unroll
            for (int i = 0; i < 2; i++) {
                int row = srow + i * 64;
                cp_async16(sbase + (uint32_t)((nbuf * SAW + row * RS + sc16) * 4),
                           gA + (size_t)row * HID2 + kb + sc16);
                cp_async16(sbase + (uint32_t)((2 * SAW + nbuf * SBW + row * RS + sc16) * 4),
                           gB + (size_t)row * HID2 + kb + sc16);
            }
            cp_commit();
            cp_wait<1>();
        } else {
            cp_wait<0>();
        }
        __syncthreads();

        uint32_t abase = sbase + (uint32_t)(buf * SAW * 4);
        uint32_t bbase = sbase + (uint32_t)((2 * SAW + buf * SBW) * 4);

#pragma unroll
        for (int kk = 0; kk < 2; kk++) {           // 2 k16 steps per stage
            uint32_t af[4][4];
#pragma unroll
            for (int mt = 0; mt < 4; mt++)
                ldsm_x4(af[mt], abase +
                        (uint32_t)(((a_row + mt * 16) * RS + kk * 8 + a_kw) * 4));
            uint32_t bf[2][4];
#pragma unroll
            for (int p = 0; p < 2; p++)
                ldsm_x4(bf[p], bbase +
                        (uint32_t)(((b_row + p * 16) * RS + kk * 8 + b_kw) * 4));
#pragma unroll
            for (int mt = 0; mt < 4; mt++)
#pragma unroll
                for (int nt = 0; nt < 4; nt++)
                    mma_f16acc(acch[mt][nt], af[mt], &bf[nt >> 1][(nt & 1) * 2]);
        }
        __syncthreads();
    }

    // epilogue: single drain + bias + candidate filter (no score store)
#pragma unroll
    for (int mt = 0; mt < 4; mt++) {
        float a4[4][4];
#pragma unroll
        for (int nt = 0; nt < 4; nt++) {
            float2 lo = __half22float2(*(__half2*)&acch[mt][nt][0]);
            float2 hi = __half22float2(*(__half2*)&acch[mt][nt][1]);
            a4[nt][0] = lo.x; a4[nt][1] = lo.y;
            a4[nt][2] = hi.x; a4[nt][3] = hi.y;
        }
#pragma unroll
        for (int c = 0; c < 4; c++) {
            int m_loc = wm * 64 + mt * 16 + g + ((c & 2) ? 8 : 0);
            float flo = floor_s[m_loc];
            int m = m0 + m_loc;
#pragma unroll
            for (int nt = 0; nt < 4; nt++) {
                int n_loc = wn * 32 + nt * 8 + 2 * tg + (c & 1);
                float s = a4[nt][c] + bias_s[n_loc];
                if (s >= flo) {
                    unsigned pos = atomicAdd(&g_ccnt[m], 1u);
                    if (pos < CAND2)
                        g_cand[(size_t)m * CAND2 + pos] =
                            packc(f2key(s), (unsigned)(n0 + n_loc));
                }
            }
        }
    }
}

// ---------------------------------------------------------------------------
// Kernel 4: complexity net -> budget[token]
// ---------------------------------------------------------------------------
__global__ void budget_kernel(const float* __restrict__ x,
                              const float* __restrict__ Wc1,
                              const float* __restrict__ bc1,
                              const float* __restrict__ Wc2,
                              const float* __restrict__ bc2) {
    __shared__ float xs[16][DIM];
    __shared__ float red[16][CHID];
    int tid = threadIdx.x;            // 0..127
    int t0  = blockIdx.x * 16;

    const float4* xsrc = (const float4*)(x + (size_t)t0 * DIM);
    float4* xdst = (float4*)&xs[0][0];
    for (int i = tid; i < 16 * DIM / 4; i += 128) xdst[i] = xsrc[i];
    __syncthreads();

    float acc[16];
#pragma unroll
    for (int m = 0; m < 16; m++) acc[m] = 0.f;

    for (int i = 0; i < DIM; i += 4) {
        float w0 = Wc1[(i + 0) * CHID + tid];
        float w1 = Wc1[(i + 1) * CHID + tid];
        float w2 = Wc1[(i + 2) * CHID + tid];
        float w3 = Wc1[(i + 3) * CHID + tid];
#pragma unroll
        for (int m = 0; m < 16; m++) {
            float4 xv = *(const float4*)&xs[m][i];
            acc[m] += xv.x * w0 + xv.y * w1 + xv.z * w2 + xv.w * w3;
        }
    }

    float b1  = bc1[tid];
    float wc2 = Wc2[tid];
#pragma unroll
    for (int m = 0; m < 16; m++) red[m][tid] = fmaxf(acc[m] + b1, 0.f) * wc2;
    __syncthreads();

    if (tid < 16) {
        float s = bc2[0];
        for (int t = 0; t < CHID; t++) s += red[tid][t];
        float sig   = 1.f / (1.f + expf(-s));
        float scale = sig * sig;
        float raw   = 100.f + 156.f * scale;
        raw = fminf(fmaxf(raw, 100.f), 256.f);
        g_budget[t0 + tid] = (int)rintf(raw);
    }
}

// ---------------------------------------------------------------------------
// Kernel 5: fallback — exact fp32 rescan for tokens with anomalous counts.
// Early-exits in the normal case.
// ---------------------------------------------------------------------------
#define HB 8192
__global__ void fallback_kernel(const float* __restrict__ Ws2,
                                const float* __restrict__ bs2) {
    int tok = blockIdx.x;
    unsigned cnt0 = g_ccnt[tok];
    if (cnt0 >= KSEL && cnt0 <= CAND2) return;

    __shared__ float    hs[HIDDEN];
    __shared__ unsigned hist[HB];
    __shared__ unsigned bsum[256];
    __shared__ unsigned s_thresh, s_cnt;
    int tid = threadIdx.x;            // 0..255

    for (int i = tid; i < HIDDEN; i += 256) hs[i] = g_h[(size_t)tok * HIDDEN + i];
    for (int i = tid; i < HB; i += 256) hist[i] = 0;
    if (tid == 0) s_cnt = 0;
    __syncthreads();

    for (int j0 = 0; j0 < POOLSZ; j0 += 256) {
        int j = j0 + tid;
        float s = bs2[j];
        for (int k = 0; k < HIDDEN; k += 4) {
            float4 hv = *(const float4*)&hs[k];
            s += hv.x * Ws2[(size_t)(k + 0) * POOLSZ + j];
            s += hv.y * Ws2[(size_t)(k + 1) * POOLSZ + j];
            s += hv.z * Ws2[(size_t)(k + 2) * POOLSZ + j];
            s += hv.w * Ws2[(size_t)(k + 3) * POOLSZ + j];
        }
        atomicAdd(&hist[f2key(s) >> 19], 1u);
    }
    __syncthreads();

    unsigned local = 0;
    int bb = tid * 32;
#pragma unroll
    for (int b = 0; b < 32; b++) local += hist[bb + b];
    bsum[tid] = local;
    __syncthreads();
    if (tid == 0) {
        unsigned cum = 0;
        int blk = 255;
        for (; blk > 0; blk--) {
            if (cum + bsum[blk] >= KSEL) break;
            cum += bsum[blk];
        }
        int b = blk * 32 + 31;
        for (;; b--) {
            unsigned c = hist[b];
            if (cum + c >= KSEL || b == 0) break;
            cum += c;
        }
        s_thresh = (unsigned)b << 19;
    }
    __syncthreads();
    unsigned th = s_thresh;

    for (int j0 = 0; j0 < POOLSZ; j0 += 256) {
        int j = j0 + tid;
        float s = bs2[j];
        for (int k = 0; k < HIDDEN; k += 4) {
            float4 hv = *(const float4*)&hs[k];
            s += hv.x * Ws2[(size_t)(k + 0) * POOLSZ + j];
            s += hv.y * Ws2[(size_t)(k + 1) * POOLSZ + j];
            s += hv.z * Ws2[(size_t)(k + 2) * POOLSZ + j];
            s += hv.w * Ws2[(size_t)(k + 3) * POOLSZ + j];
        }
        unsigned key = f2key(s);
        if (key >= th) {
            unsigned pos = atomicAdd(&s_cnt, 1u);
            if (pos < CAND2)
                g_cand[(size_t)tok * CAND2 + pos] = packc(key, (unsigned)j);
        }
    }
    __syncthreads();
    if (tid == 0) {
        unsigned c = s_cnt;
        g_ccnt[tok] = (c > CAND2) ? CAND2 : c;
    }
}

// ---------------------------------------------------------------------------
// Kernel 6: per-token select: bitonic sort of <=1024 packed candidates,
// softmax over top-256, budget mask.
// ---------------------------------------------------------------------------
#define TPS 512
__global__ void select_kernel() {
    __shared__ unsigned long long c[CAND2];
    __shared__ float red[256];
    int tid = threadIdx.x;
    int tok = blockIdx.x;

    unsigned cnt = g_ccnt[tok];
    if (cnt > CAND2) cnt = CAND2;
    for (int i = tid; i < CAND2; i += TPS)
        c[i] = (i < (int)cnt) ? g_cand[(size_t)tok * CAND2 + i] : 0ULL;
    __syncthreads();

    for (unsigned k = 2; k <= CAND2; k <<= 1) {
        for (unsigned j = k >> 1; j > 0; j >>= 1) {
            for (unsigned i = tid; i < CAND2; i += TPS) {
                unsigned ixj = i ^ j;
                if (ixj > i) {
                    bool up = ((i & k) == 0);
                    unsigned long long a = c[i], b = c[ixj];
                    if (up ? (a > b) : (a < b)) { c[i] = b; c[ixj] = a; }
                }
            }
            __syncthreads();
        }
    }

    int bud = g_budget[tok];
    float smax = key2f((unsigned)(c[CAND2 - 1] >> 32));
    float ex = 0.f;
    unsigned long long v = 0ULL;
    if (tid < 256) {
        v  = c[CAND2 - 1 - tid];
        ex = expf(key2f((unsigned)(v >> 32)) - smax);
        red[tid] = ex;
    }
    __syncthreads();
    for (int s = 128; s > 0; s >>= 1) {
        if (tid < s) red[tid] += red[tid + s];
        __syncthreads();
    }
    if (tid < 256) {
        float w = ex / red[0];
        if (tid >= bud) w = 0.f;
        g_topidx[(size_t)tok * KSEL + tid] = (int)(0xFFFFFFFFu - (unsigned)(v & 0xFFFFFFFFull));
        g_topw[(size_t)tok * KSEL + tid]   = w;
    }
}

// ---------------------------------------------------------------------------
// Kernel 7: executor (float4 gather)
// ---------------------------------------------------------------------------
__global__ void executor_kernel(const float* __restrict__ x,
                                const float* __restrict__ pool,
                                float* __restrict__ out) {
    __shared__ float xs[DIM];
    __shared__ float partial[8][DIM];
    int tok  = blockIdx.x;
    int tid  = threadIdx.x;
    int warp = tid >> 5;
    int lane = tid & 31;

    for (int i = tid; i < DIM; i += 256) xs[i] = x[(size_t)tok * DIM + i];
    __syncthreads();

    float4 acc4[4];
#pragma unroll
    for (int j = 0; j < 4; j++) acc4[j] = make_float4(0.f, 0.f, 0.f, 0.f);

    const float4* xs4 = (const float4*)xs;
    for (int k = warp; k < KSEL; k += 8) {
        float w = g_topw[(size_t)tok * KSEL + k];
        if (w != 0.f) {
            int idx = g_topidx[(size_t)tok * KSEL + k];
            const float4* row = (const float4*)(pool + (size_t)idx * DIM);
            float4 r[4];
            float p = 0.f;
#pragma unroll
            for (int j = 0; j < 4; j++) {
                r[j] = __ldg(row + lane + 32 * j);
                float4 xv = xs4[lane + 32 * j];
                p += xv.x * r[j].x + xv.y * r[j].y + xv.z * r[j].z + xv.w * r[j].w;
            }
#pragma unroll
            for (int off = 16; off > 0; off >>= 1)
                p += __shfl_xor_sync(0xffffffffu, p, off);
            float act = tanhf(p) * w;
#pragma unroll
            for (int j = 0; j < 4; j++) {
                acc4[j].x += act * r[j].x;
                acc4[j].y += act * r[j].y;
                acc4[j].z += act * r[j].z;
                acc4[j].w += act * r[j].w;
            }
        }
    }

    float4* part4 = (float4*)&partial[warp][0];
#pragma unroll
    for (int j = 0; j < 4; j++) part4[lane + 32 * j] = acc4[j];
    __syncthreads();

    for (int e = tid; e < DIM; e += 256) {
        float s = xs[e];
#pragma unroll
        for (int wp = 0; wp < 8; wp++) s += partial[wp][e];
        out[(size_t)tok * DIM + e] = s;
    }
}

// ---------------------------------------------------------------------------
extern "C" void kernel_launch(void* const* d_in, const int* in_sizes, int n_in,
                              void* d_out, int out_size) {
    const float* x    = (const float*)d_in[0];
    const float* pool = (const float*)d_in[1];
    const float* Wc1  = (const float*)d_in[2];
    const float* bc1  = (const float*)d_in[3];
    const float* Wc2  = (const float*)d_in[4];
    const float* bc2  = (const float*)d_in[5];
    const float* Ws1  = (const float*)d_in[6];
    const float* bs1  = (const float*)d_in[7];
    const float* Ws2  = (const float*)d_in[8];
    const float* bs2  = (const float*)d_in[9];
    float* out = (float*)d_out;

    cudaFuncSetAttribute(gemm_kernel,
                         cudaFuncAttributeMaxDynamicSharedMemorySize,
                         GEMM_SMEM_BYTES);

    dim3 tg(POOLSZ / 64, HIDDEN / 64);
    w2h_kernel<<<tg, 256>>>(Ws2);                                  // 1
    hidden_kernel<<<N_TOK / 16, 256>>>(x, Ws1, bs1);               // 2
    floor_kernel<<<N_TOK / 8, 256>>>();                            // 3

    dim3 ggrid(N_TOK / BM, POOLSZ / BN);   // x = m fast -> B slice reused in L2
    gemm_kernel<<<ggrid, 256, GEMM_SMEM_BYTES>>>(bs2);             // 4 (profiled slot)

    budget_kernel<<<N_TOK / 16, 128>>>(x, Wc1, bc1, Wc2, bc2);     // 5
    fallback_kernel<<<N_TOK, 256>>>(Ws2, bs2);                     // 6
    select_kernel<<<N_TOK, TPS>>>();                               // 7
    executor_kernel<<<N_TOK, 256>>>(x, pool, out);                 // 8
}

// round 17
// speedup vs baseline: 2.4715x; 1.0111x over previous
#include <cuda_runtime.h>
#include <cuda_fp16.h>
#include <math.h>
#include <stdint.h>

// Problem constants
#define N_TOK   2048
#define DIM     512
#define POOLSZ  65536
#define HIDDEN  256
#define HID2    128         // HIDDEN/2 (f16 pair words)
#define CHID    128
#define KSEL    256
#define CAND2   1024        // candidate buffer depth per token
#define FLOORZ  2.4f        // floor = FLOORZ*sigma  (E[count]=537, sd=23)
#define FMARG   0.03f       // f16 full-K accum filter margin (~20 sigma_err)

// GEMM tiling (f16 mma.sync m16n8k16, f16 accum, single final drain)
#define BM 128
#define BN 128
#define BKW 16              // k-pair words per stage (= 32 f16 k), 8 stages
#define NSTG 3              // ring depth
#define NIT  (HID2 / BKW)   // 8 iterations
#define RS 20               // smem row stride words (16 data + 4 pad; 5i mod 32 distinct)
#define SAW (BM * RS)       // 2560 words per A stage
#define SBW (BN * RS)       // 2560 words per B stage
#define STG (SAW + SBW)     // words per ring slot
#define GEMM_SMEM_WORDS (NSTG * STG + BN + BM)
#define GEMM_SMEM_BYTES (GEMM_SMEM_WORDS * 4)

// Device scratch
__device__ float              g_h[N_TOK * HIDDEN];            // fp32 hidden (floor, fallback)
__device__ unsigned           g_hh[N_TOK * HID2];             // f16x2 hidden, k-major rows
__device__ unsigned           g_w2h[(size_t)POOLSZ * HID2];   // f16x2 Ws2^T rows [n][k] (32 MB)
__device__ float              g_floor[N_TOK];
__device__ unsigned           g_ccnt[N_TOK];
__device__ unsigned long long g_cand[(size_t)N_TOK * CAND2];
__device__ int                g_budget[N_TOK];
__device__ int                g_topidx[N_TOK * KSEL];
__device__ float              g_topw[N_TOK * KSEL];

// key helpers: monotonic float->uint mapping
__device__ __forceinline__ unsigned f2key(float s) {
    unsigned u = __float_as_uint(s);
    return (u & 0x80000000u) ? ~u : (u | 0x80000000u);
}
__device__ __forceinline__ float key2f(unsigned k) {
    return (k & 0x80000000u) ? __uint_as_float(k ^ 0x80000000u)
                             : __uint_as_float(~k);
}
__device__ __forceinline__ unsigned long long packc(unsigned key, unsigned idx) {
    return ((unsigned long long)key << 32) | (unsigned long long)(0xFFFFFFFFu - idx);
}
__device__ __forceinline__ unsigned packh(float lo, float hi) {
    __half2 t = __floats2half2_rn(lo, hi);
    return *(unsigned*)&t;
}

__device__ __forceinline__ void cp_async16(uint32_t saddr, const void* gaddr) {
    asm volatile("cp.async.cg.shared.global [%0], [%1], 16;\n"
                 :: "r"(saddr), "l"(gaddr));
}
__device__ __forceinline__ void cp_commit() {
    asm volatile("cp.async.commit_group;\n");
}
template <int N> __device__ __forceinline__ void cp_wait() {
    asm volatile("cp.async.wait_group %0;\n" :: "n"(N));
}
__device__ __forceinline__ void ldsm_x4(uint32_t* r, uint32_t addr) {
    asm volatile("ldmatrix.sync.aligned.m8n8.x4.shared.b16 {%0,%1,%2,%3}, [%4];"
                 : "=r"(r[0]), "=r"(r[1]), "=r"(r[2]), "=r"(r[3]) : "r"(addr));
}
// f16 x f16 -> f16 accumulate (double-rate legacy-pipe path)
__device__ __forceinline__ void mma_f16acc(uint32_t* d, const uint32_t* a,
                                           const uint32_t* b) {
    asm volatile(
        "mma.sync.aligned.m16n8k16.row.col.f16.f16.f16.f16 "
        "{%0,%1}, {%2,%3,%4,%5}, {%6,%7}, {%0,%1};"
        : "+r"(d[0]), "+r"(d[1])
        : "r"(a[0]), "r"(a[1]), "r"(a[2]), "r"(a[3]), "r"(b[0]), "r"(b[1]));
}

// ---------------------------------------------------------------------------
// Kernel 0: transpose-convert Ws2 fp32 [HIDDEN][POOLSZ] -> f16x2 rows [n][k]
// ---------------------------------------------------------------------------
__global__ void w2h_kernel(const float* __restrict__ Ws2) {
    __shared__ float ts[64][65];
    int tid = threadIdx.x;            // 0..255
    int n0 = blockIdx.x * 64;
    int k0 = blockIdx.y * 64;

#pragma unroll
    for (int i = 0; i < 16; i++) {
        int idx = tid + i * 256;
        int k = idx >> 6, n = idx & 63;
        ts[k][n] = Ws2[(size_t)(k0 + k) * POOLSZ + n0 + n];
    }
    __syncthreads();

#pragma unroll
    for (int i = 0; i < 8; i++) {
        int idx = tid + i * 256;
        int n = idx >> 5, w = idx & 31;
        g_w2h[(size_t)(n0 + n) * HID2 + (k0 >> 1) + w] =
            packh(ts[2 * w][n], ts[2 * w + 1][n]);
    }
}

// ---------------------------------------------------------------------------
// Kernel 1: scorer hidden h = relu(x @ Ws1 + bs1); stores fp32 + f16x2
// ---------------------------------------------------------------------------
__global__ void hidden_kernel(const float* __restrict__ x,
                              const float* __restrict__ Ws1,
                              const float* __restrict__ bs1) {
    __shared__ float xs[16][DIM];
    int tid = threadIdx.x;            // 0..255 (= hidden unit)
    int t0  = blockIdx.x * 16;

    const float4* xsrc = (const float4*)(x + (size_t)t0 * DIM);
    float4* xdst = (float4*)&xs[0][0];
    for (int i = tid; i < 16 * DIM / 4; i += 256) xdst[i] = xsrc[i];
    __syncthreads();

    float acc[16];
#pragma unroll
    for (int m = 0; m < 16; m++) acc[m] = 0.f;

    for (int i = 0; i < DIM; i += 4) {
        float w0 = Ws1[(i + 0) * HIDDEN + tid];
        float w1 = Ws1[(i + 1) * HIDDEN + tid];
        float w2 = Ws1[(i + 2) * HIDDEN + tid];
        float w3 = Ws1[(i + 3) * HIDDEN + tid];
#pragma unroll
        for (int m = 0; m < 16; m++) {
            float4 xv = *(const float4*)&xs[m][i];
            acc[m] += xv.x * w0 + xv.y * w1 + xv.z * w2 + xv.w * w3;
        }
    }

    float b = bs1[tid];
#pragma unroll
    for (int m = 0; m < 16; m++) {
        float hv = fmaxf(acc[m] + b, 0.f);
        g_h[(size_t)(t0 + m) * HIDDEN + tid] = hv;
        float other = __shfl_xor_sync(0xffffffffu, hv, 1);
        if ((tid & 1) == 0)
            g_hh[(size_t)(t0 + m) * HID2 + (tid >> 1)] = packh(hv, other);
    }
}

// ---------------------------------------------------------------------------
// Kernel 2: per-token floor = FLOORZ*||h||/16 - FMARG; zero candidate counter
// ---------------------------------------------------------------------------
__global__ void floor_kernel() {
    int tok  = blockIdx.x * 8 + (threadIdx.x >> 5);
    int lane = threadIdx.x & 31;
    const float* h = g_h + (size_t)tok * HIDDEN;
    float s = 0.f;
    for (int i = lane; i < HIDDEN; i += 32) { float v = h[i]; s += v * v; }
#pragma unroll
    for (int off = 16; off > 0; off >>= 1)
        s += __shfl_xor_sync(0xffffffffu, s, off);
    if (lane == 0) {
        g_floor[tok] = FLOORZ * sqrtf(s) * (1.0f / 16.0f) - FMARG;
        g_ccnt[tok]  = 0;
    }
}

// ---------------------------------------------------------------------------
// Kernel 3: f16 mma.sync GEMM, f16 accumulators across full K, triple-buffered
// ring (ONE barrier per stage), ldmatrix loads, fused candidate filter.
// CTA 128x128, 8 warps (2m x 4n), warp tile 64x32, 3 CTAs/SM.
// ---------------------------------------------------------------------------
__global__ __launch_bounds__(256, 3) void gemm_kernel(const float* __restrict__ bs2) {
    extern __shared__ unsigned smem[];             // word-addressed
    float* bias_s  = (float*)(smem + NSTG * STG);
    float* floor_s = bias_s + BN;

    int tid  = threadIdx.x;
    int warp = tid >> 5, lane = tid & 31;
    int wm = warp >> 2, wn = warp & 3;             // 2 x 4 warps
    int g  = lane >> 2, tg = lane & 3;
    int m0 = blockIdx.x * BM;
    int n0 = blockIdx.y * BN;

    for (int i = tid; i < BN; i += 256) bias_s[i]  = bs2[n0 + i];
    for (int i = tid; i < BM; i += 256) floor_s[i] = g_floor[m0 + i];

    uint32_t sbase = (uint32_t)__cvta_generic_to_shared(smem);
    const unsigned* gA = g_hh + (size_t)m0 * HID2;
    const unsigned* gB = g_w2h + (size_t)n0 * HID2;

    // staging: 512 16B chunks per operand per stage; 2 chunks/thread each
    int srow = tid >> 2;                 // 0..63 -> rows srow, srow+64
    int sc16 = (tid & 3) << 2;           // word quad within 16-word k row

    int lmat = lane >> 3;                // ldmatrix constants
    int lrow = lane & 7;
    int a_row = wm * 64 + (lmat & 1) * 8 + lrow;
    int a_kw  = (lmat >> 1) * 4;
    int b_row = wn * 32 + (lmat >> 1) * 8 + lrow;
    int b_kw  = (lmat & 1) * 4;

    // stage-issue helper (stage s -> ring slot s % NSTG)
    auto issue_stage = [&](int s) {
        int slot = s % NSTG;
        int kb = s * BKW;
        uint32_t abuf = sbase + (uint32_t)((slot * STG) * 4);
        uint32_t bbuf = sbase + (uint32_t)((slot * STG + SAW) * 4);
#pragma unroll
        for (int i = 0; i < 2; i++) {
            int row = srow + i * 64;
            cp_async16(abuf + (uint32_t)((row * RS + sc16) * 4),
                       gA + (size_t)row * HID2 + kb + sc16);
            cp_async16(bbuf + (uint32_t)((row * RS + sc16) * 4),
                       gB + (size_t)row * HID2 + kb + sc16);
        }
        cp_commit();
    };

    // prologue: stages 0 and 1 in flight
    issue_stage(0);
    issue_stage(1);

    // f16 accumulators, carried across all stages (256 K terms)
    uint32_t acch[4][4][2];
#pragma unroll
    for (int mt = 0; mt < 4; mt++)
#pragma unroll
        for (int nt = 0; nt < 4; nt++)
            acch[mt][nt][0] = acch[mt][nt][1] = 0u;

    for (int it = 0; it < NIT; it++) {
        if (it < NIT - 1) cp_wait<1>();            // stage it complete
        else              cp_wait<0>();
        __syncthreads();                           // single barrier per stage
        if (it + 2 < NIT) issue_stage(it + 2);     // safe: slot (it+2)%3 untouched

        int slot = it % NSTG;
        uint32_t abase = sbase + (uint32_t)((slot * STG) * 4);
        uint32_t bbase = sbase + (uint32_t)((slot * STG + SAW) * 4);

#pragma unroll
        for (int kk = 0; kk < 2; kk++) {           // 2 k16 steps per stage
            uint32_t af[4][4];
#pragma unroll
            for (int mt = 0; mt < 4; mt++)
                ldsm_x4(af[mt], abase +
                        (uint32_t)(((a_row + mt * 16) * RS + kk * 8 + a_kw) * 4));
            uint32_t bf[2][4];
#pragma unroll
            for (int p = 0; p < 2; p++)
                ldsm_x4(bf[p], bbase +
                        (uint32_t)(((b_row + p * 16) * RS + kk * 8 + b_kw) * 4));
#pragma unroll
            for (int mt = 0; mt < 4; mt++)
#pragma unroll
                for (int nt = 0; nt < 4; nt++)
                    mma_f16acc(acch[mt][nt], af[mt], &bf[nt >> 1][(nt & 1) * 2]);
        }
    }

    // epilogue: single drain + bias + candidate filter (no score store)
#pragma unroll
    for (int mt = 0; mt < 4; mt++) {
        float a4[4][4];
#pragma unroll
        for (int nt = 0; nt < 4; nt++) {
            float2 lo = __half22float2(*(__half2*)&acch[mt][nt][0]);
            float2 hi = __half22float2(*(__half2*)&acch[mt][nt][1]);
            a4[nt][0] = lo.x; a4[nt][1] = lo.y;
            a4[nt][2] = hi.x; a4[nt][3] = hi.y;
        }
#pragma unroll
        for (int c = 0; c < 4; c++) {
            int m_loc = wm * 64 + mt * 16 + g + ((c & 2) ? 8 : 0);
            float flo = floor_s[m_loc];
            int m = m0 + m_loc;
#pragma unroll
            for (int nt = 0; nt < 4; nt++) {
                int n_loc = wn * 32 + nt * 8 + 2 * tg + (c & 1);
                float s = a4[nt][c] + bias_s[n_loc];
                if (s >= flo) {
                    unsigned pos = atomicAdd(&g_ccnt[m], 1u);
                    if (pos < CAND2)
                        g_cand[(size_t)m * CAND2 + pos] =
                            packc(f2key(s), (unsigned)(n0 + n_loc));
                }
            }
        }
    }
}

// ---------------------------------------------------------------------------
// Kernel 4: complexity net -> budget[token]
// ---------------------------------------------------------------------------
__global__ void budget_kernel(const float* __restrict__ x,
                              const float* __restrict__ Wc1,
                              const float* __restrict__ bc1,
                              const float* __restrict__ Wc2,
                              const float* __restrict__ bc2) {
    __shared__ float xs[16][DIM];
    __shared__ float red[16][CHID];
    int tid = threadIdx.x;            // 0..127
    int t0  = blockIdx.x * 16;

    const float4* xsrc = (const float4*)(x + (size_t)t0 * DIM);
    float4* xdst = (float4*)&xs[0][0];
    for (int i = tid; i < 16 * DIM / 4; i += 128) xdst[i] = xsrc[i];
    __syncthreads();

    float acc[16];
#pragma unroll
    for (int m = 0; m < 16; m++) acc[m] = 0.f;

    for (int i = 0; i < DIM; i += 4) {
        float w0 = Wc1[(i + 0) * CHID + tid];
        float w1 = Wc1[(i + 1) * CHID + tid];
        float w2 = Wc1[(i + 2) * CHID + tid];
        float w3 = Wc1[(i + 3) * CHID + tid];
#pragma unroll
        for (int m = 0; m < 16; m++) {
            float4 xv = *(const float4*)&xs[m][i];
            acc[m] += xv.x * w0 + xv.y * w1 + xv.z * w2 + xv.w * w3;
        }
    }

    float b1  = bc1[tid];
    float wc2 = Wc2[tid];
#pragma unroll
    for (int m = 0; m < 16; m++) red[m][tid] = fmaxf(acc[m] + b1, 0.f) * wc2;
    __syncthreads();

    if (tid < 16) {
        float s = bc2[0];
        for (int t = 0; t < CHID; t++) s += red[tid][t];
        float sig   = 1.f / (1.f + expf(-s));
        float scale = sig * sig;
        float raw   = 100.f + 156.f * scale;
        raw = fminf(fmaxf(raw, 100.f), 256.f);
        g_budget[t0 + tid] = (int)rintf(raw);
    }
}

// ---------------------------------------------------------------------------
// Kernel 5: fallback — exact fp32 rescan for tokens with anomalous counts.
// Early-exits in the normal case.
// ---------------------------------------------------------------------------
#define HB 8192
__global__ void fallback_kernel(const float* __restrict__ Ws2,
                                const float* __restrict__ bs2) {
    int tok = blockIdx.x;
    unsigned cnt0 = g_ccnt[tok];
    if (cnt0 >= KSEL && cnt0 <= CAND2) return;

    __shared__ float    hs[HIDDEN];
    __shared__ unsigned hist[HB];
    __shared__ unsigned bsum[256];
    __shared__ unsigned s_thresh, s_cnt;
    int tid = threadIdx.x;            // 0..255

    for (int i = tid; i < HIDDEN; i += 256) hs[i] = g_h[(size_t)tok * HIDDEN + i];
    for (int i = tid; i < HB; i += 256) hist[i] = 0;
    if (tid == 0) s_cnt = 0;
    __syncthreads();

    for (int j0 = 0; j0 < POOLSZ; j0 += 256) {
        int j = j0 + tid;
        float s = bs2[j];
        for (int k = 0; k < HIDDEN; k += 4) {
            float4 hv = *(const float4*)&hs[k];
            s += hv.x * Ws2[(size_t)(k + 0) * POOLSZ + j];
            s += hv.y * Ws2[(size_t)(k + 1) * POOLSZ + j];
            s += hv.z * Ws2[(size_t)(k + 2) * POOLSZ + j];
            s += hv.w * Ws2[(size_t)(k + 3) * POOLSZ + j];
        }
        atomicAdd(&hist[f2key(s) >> 19], 1u);
    }
    __syncthreads();

    unsigned local = 0;
    int bb = tid * 32;
#pragma unroll
    for (int b = 0; b < 32; b++) local += hist[bb + b];
    bsum[tid] = local;
    __syncthreads();
    if (tid == 0) {
        unsigned cum = 0;
        int blk = 255;
        for (; blk > 0; blk--) {
            if (cum + bsum[blk] >= KSEL) break;
            cum += bsum[blk];
        }
        int b = blk * 32 + 31;
        for (;; b--) {
            unsigned c = hist[b];
            if (cum + c >= KSEL || b == 0) break;
            cum += c;
        }
        s_thresh = (unsigned)b << 19;
    }
    __syncthreads();
    unsigned th = s_thresh;

    for (int j0 = 0; j0 < POOLSZ; j0 += 256) {
        int j = j0 + tid;
        float s = bs2[j];
        for (int k = 0; k < HIDDEN; k += 4) {
            float4 hv = *(const float4*)&hs[k];
            s += hv.x * Ws2[(size_t)(k + 0) * POOLSZ + j];
            s += hv.y * Ws2[(size_t)(k + 1) * POOLSZ + j];
            s += hv.z * Ws2[(size_t)(k + 2) * POOLSZ + j];
            s += hv.w * Ws2[(size_t)(k + 3) * POOLSZ + j];
        }
        unsigned key = f2key(s);
        if (key >= th) {
            unsigned pos = atomicAdd(&s_cnt, 1u);
            if (pos < CAND2)
                g_cand[(size_t)tok * CAND2 + pos] = packc(key, (unsigned)j);
        }
    }
    __syncthreads();
    if (tid == 0) {
        unsigned c = s_cnt;
        g_ccnt[tok] = (c > CAND2) ? CAND2 : c;
    }
}

// ---------------------------------------------------------------------------
// Kernel 6: per-token select: bitonic sort of <=1024 packed candidates,
// softmax over top-256, budget mask.
// ---------------------------------------------------------------------------
#define TPS 512
__global__ void select_kernel() {
    __shared__ unsigned long long c[CAND2];
    __shared__ float red[256];
    int tid = threadIdx.x;
    int tok = blockIdx.x;

    unsigned cnt = g_ccnt[tok];
    if (cnt > CAND2) cnt = CAND2;
    for (int i = tid; i < CAND2; i += TPS)
        c[i] = (i < (int)cnt) ? g_cand[(size_t)tok * CAND2 + i] : 0ULL;
    __syncthreads();

    for (unsigned k = 2; k <= CAND2; k <<= 1) {
        for (unsigned j = k >> 1; j > 0; j >>= 1) {
            for (unsigned i = tid; i < CAND2; i += TPS) {
                unsigned ixj = i ^ j;
                if (ixj > i) {
                    bool up = ((i & k) == 0);
                    unsigned long long a = c[i], b = c[ixj];
                    if (up ? (a > b) : (a < b)) { c[i] = b; c[ixj] = a; }
                }
            }
            __syncthreads();
        }
    }

    int bud = g_budget[tok];
    float smax = key2f((unsigned)(c[CAND2 - 1] >> 32));
    float ex = 0.f;
    unsigned long long v = 0ULL;
    if (tid < 256) {
        v  = c[CAND2 - 1 - tid];
        ex = expf(key2f((unsigned)(v >> 32)) - smax);
        red[tid] = ex;
    }
    __syncthreads();
    for (int s = 128; s > 0; s >>= 1) {
        if (tid < s) red[tid] += red[tid + s];
        __syncthreads();
    }
    if (tid < 256) {
        float w = ex / red[0];
        if (tid >= bud) w = 0.f;
        g_topidx[(size_t)tok * KSEL + tid] = (int)(0xFFFFFFFFu - (unsigned)(v & 0xFFFFFFFFull));
        g_topw[(size_t)tok * KSEL + tid]   = w;
    }
}

// ---------------------------------------------------------------------------
// Kernel 7: executor (float4 gather, two rows in flight per warp)
// ---------------------------------------------------------------------------
__global__ void executor_kernel(const float* __restrict__ x,
                                const float* __restrict__ pool,
                                float* __restrict__ out) {
    __shared__ float xs[DIM];
    __shared__ float partial[8][DIM];
    int tok  = blockIdx.x;
    int tid  = threadIdx.x;
    int warp = tid >> 5;
    int lane = tid & 31;

    for (int i = tid; i < DIM; i += 256) xs[i] = x[(size_t)tok * DIM + i];
    __syncthreads();

    float4 acc4[4];
#pragma unroll
    for (int j = 0; j < 4; j++) acc4[j] = make_float4(0.f, 0.f, 0.f, 0.f);

    const float4* xs4 = (const float4*)xs;
    for (int k = warp; k < KSEL; k += 16) {
        int k2 = k + 8;
        float w1 = g_topw[(size_t)tok * KSEL + k];
        float w2 = g_topw[(size_t)tok * KSEL + k2];
        const float4* row1 = nullptr;
        const float4* row2 = nullptr;
        if (w1 != 0.f)
            row1 = (const float4*)(pool + (size_t)g_topidx[(size_t)tok * KSEL + k] * DIM);
        if (w2 != 0.f)
            row2 = (const float4*)(pool + (size_t)g_topidx[(size_t)tok * KSEL + k2] * DIM);

        float4 r1[4], r2[4];
        float p1 = 0.f, p2 = 0.f;
        if (row1) {
#pragma unroll
            for (int j = 0; j < 4; j++) r1[j] = __ldg(row1 + lane + 32 * j);
        }
        if (row2) {
#pragma unroll
            for (int j = 0; j < 4; j++) r2[j] = __ldg(row2 + lane + 32 * j);
        }
        if (row1) {
#pragma unroll
            for (int j = 0; j < 4; j++) {
                float4 xv = xs4[lane + 32 * j];
                p1 += xv.x * r1[j].x + xv.y * r1[j].y + xv.z * r1[j].z + xv.w * r1[j].w;
            }
        }
        if (row2) {
#pragma unroll
            for (int j = 0; j < 4; j++) {
                float4 xv = xs4[lane + 32 * j];
                p2 += xv.x * r2[j].x + xv.y * r2[j].y + xv.z * r2[j].z + xv.w * r2[j].w;
            }
        }
#pragma unroll
        for (int off = 16; off > 0; off >>= 1) {
            p1 += __shfl_xor_sync(0xffffffffu, p1, off);
            p2 += __shfl_xor_sync(0xffffffffu, p2, off);
        }
        if (row1) {
            float act = tanhf(p1) * w1;
#pragma unroll
            for (int j = 0; j < 4; j++) {
                acc4[j].x += act * r1[j].x;
                acc4[j].y += act * r1[j].y;
                acc4[j].z += act * r1[j].z;
                acc4[j].w += act * r1[j].w;
            }
        }
        if (row2) {
            float act = tanhf(p2) * w2;
#pragma unroll
            for (int j = 0; j < 4; j++) {
                acc4[j].x += act * r2[j].x;
                acc4[j].y += act * r2[j].y;
                acc4[j].z += act * r2[j].z;
                acc4[j].w += act * r2[j].w;
            }
        }
    }

    float4* part4 = (float4*)&partial[warp][0];
#pragma unroll
    for (int j = 0; j < 4; j++) part4[lane + 32 * j] = acc4[j];
    __syncthreads();

    for (int e = tid; e < DIM; e += 256) {
        float s = xs[e];
#pragma unroll
        for (int wp = 0; wp < 8; wp++) s += partial[wp][e];
        out[(size_t)tok * DIM + e] = s;
    }
}

// ---------------------------------------------------------------------------
extern "C" void kernel_launch(void* const* d_in, const int* in_sizes, int n_in,
                              void* d_out, int out_size) {
    const float* x    = (const float*)d_in[0];
    const float* pool = (const float*)d_in[1];
    const float* Wc1  = (const float*)d_in[2];
    const float* bc1  = (const float*)d_in[3];
    const float* Wc2  = (const float*)d_in[4];
    const float* bc2  = (const float*)d_in[5];
    const float* Ws1  = (const float*)d_in[6];
    const float* bs1  = (const float*)d_in[7];
    const float* Ws2  = (const float*)d_in[8];
    const float* bs2  = (const float*)d_in[9];
    float* out = (float*)d_out;

    cudaFuncSetAttribute(gemm_kernel,
                         cudaFuncAttributeMaxDynamicSharedMemorySize,
                         GEMM_SMEM_BYTES);

    dim3 tg(POOLSZ / 64, HIDDEN / 64);
    w2h_kernel<<<tg, 256>>>(Ws2);                                  // 1
    hidden_kernel<<<N_TOK / 16, 256>>>(x, Ws1, bs1);               // 2
    floor_kernel<<<N_TOK / 8, 256>>>();                            // 3

    dim3 ggrid(N_TOK / BM, POOLSZ / BN);   // x = m fast -> B slice reused in L2
    gemm_kernel<<<ggrid, 256, GEMM_SMEM_BYTES>>>(bs2);             // 4 (profiled slot)

    budget_kernel<<<N_TOK / 16, 128>>>(x, Wc1, bc1, Wc2, bc2);     // 5
    fallback_kernel<<<N_TOK, 256>>>(Ws2, bs2);                     // 6
    select_kernel<<<N_TOK, TPS>>>();                               // 7
    executor_kernel<<<N_TOK, 256>>>(x, pool, out);                 // 8
}